// round 9
// baseline (speedup 1.0000x reference)
#include <cuda_runtime.h>
#include <cstdint>

// ---------------------------------------------------------------------------
// ImageFusion via mma.sync int8 (IMMA m16n8k32) with two-level fixed-point:
//   x ~= s * (X1 + X2/128),  X1,X2 int8
//   A@B ~= sA*sB * ( A1B1 + (A1B2 + A2B1)/128 )     [A2B2 dropped, ~2^-28]
// Int32 accumulation is exact; only input quantization (~2^-15 of fullscale)
// contributes error.  Two int32 accumulator sets: accH (A1B1), accM (cross).
// Base-ISA only (ptxas targets sm_103 without 'a' features).
// ---------------------------------------------------------------------------

#define Bb    2
#define Hh    256
#define Ww    256
#define Cc    32
#define HEADS 8
#define Mm    2048
#define Kq    2048
#define Ff    16384
#define Kf    16384
#define Nfin  2048

// ---- scratch ----
__device__ __align__(1024) int8_t g_A8[(size_t)Mm * 2 * Kq];        //   8 MB
__device__ __align__(1024) int8_t g_W8[(size_t)3 * Ff * 2 * Kq];    // 201 MB
__device__ __align__(1024) int8_t g_Wo8[(size_t)Nfin * 2 * Kf];     //  67 MB
__device__ float                  g_QKV[(size_t)3 * Mm * Ff];       // 402 MB
__device__ __align__(1024) int8_t g_O8[(size_t)Mm * 2 * Kf];        //  67 MB
__device__ float g_bP[3 * Ff + Nfin];
__device__ float g_sW[3 * Ff], g_sWr[3 * Ff];     // qkv col scales (permuted idx)
__device__ float g_sWo[Nfin], g_sWor[Nfin];       // wo col scales (permuted idx)
__device__ float g_sO[Mm];                        // O row scales
__device__ float g_SA, g_SAr;                     // global A scale

// ---------------------------------------------------------------------------
// helpers
// ---------------------------------------------------------------------------
static __device__ __forceinline__ uint32_t s2u(const void* p) {
    uint32_t a;
    asm("{ .reg .u64 t; cvta.to.shared.u64 t, %1; cvt.u32.u64 %0, t; }"
        : "=r"(a) : "l"(p));
    return a;
}
static __device__ __forceinline__ void cpa16(uint32_t dst, const void* src) {
    asm volatile("cp.async.cg.shared.global [%0], [%1], 16;\n"
                 :: "r"(dst), "l"(src));
}
static __device__ __forceinline__ void cpa_commit() {
    asm volatile("cp.async.commit_group;\n");
}
template <int N>
static __device__ __forceinline__ void cpa_wait() {
    asm volatile("cp.async.wait_group %0;\n" :: "n"(N));
}
static __device__ __forceinline__ void ldm4(uint32_t* r, uint32_t a) {
    asm volatile("ldmatrix.sync.aligned.m8n8.x4.shared.b16 {%0,%1,%2,%3}, [%4];"
                 : "=r"(r[0]), "=r"(r[1]), "=r"(r[2]), "=r"(r[3]) : "r"(a));
}
static __device__ __forceinline__ void mma_s8(int* d, const uint32_t* a,
                                              uint32_t b0, uint32_t b1) {
    asm volatile("mma.sync.aligned.m16n8k32.row.col.s32.s8.s8.s32 "
                 "{%0,%1,%2,%3}, {%4,%5,%6,%7}, {%8,%9}, {%0,%1,%2,%3};"
                 : "+r"(d[0]), "+r"(d[1]), "+r"(d[2]), "+r"(d[3])
                 : "r"(a[0]), "r"(a[1]), "r"(a[2]), "r"(a[3]), "r"(b0), "r"(b1));
}

// ---------------------------------------------------------------------------
// GEMM core: BM=128, BN=128, BK=128 bytes(s8), 256 threads (8 warps 2x4,
// warp tile 64x32), 4-stage cp.async pipeline.  SMEM atoms: 16 rows x 32B
// (512B), atom (ka, i) at (ka*8+i)*512; element (row, byte) at row*32 +
// ((byte16 ^ (row>>2)&1)<<4) + byte%16 — conflict-free stores + ldmatrix.
// ---------------------------------------------------------------------------
#define STG_A   16384
#define STG_SZ  32768
#define GSMEM   (4 * STG_SZ)

static __device__ __forceinline__ void load_stage(const int8_t* gA,
                                                  const int8_t* gB,
                                                  size_t rs, int kA, int kB,
                                                  uint32_t base, int tid) {
#pragma unroll
    for (int it = 0; it < 4; it++) {           // A: 128 rows x 8 16B-chunks
        int q = it * 256 + tid;
        int m = q >> 3, h2 = q & 7;
        uint32_t dst = base + ((h2 >> 1) * 8 + (m >> 4)) * 512 + (m & 15) * 32
                     + (((h2 & 1) ^ ((m >> 2) & 1)) << 4);
        cpa16(dst, gA + (size_t)m * rs + kA + h2 * 16);
    }
#pragma unroll
    for (int it = 0; it < 4; it++) {           // B: 128 rows x 8 16B-chunks
        int q = it * 256 + tid;
        int n = q >> 3, h2 = q & 7;
        uint32_t dst = base + STG_A + ((h2 >> 1) * 8 + (n >> 4)) * 512
                     + (n & 15) * 32 + (((h2 & 1) ^ ((n >> 2) & 1)) << 4);
        cpa16(dst, gB + (size_t)n * rs + kB + h2 * 16);
    }
}

static __device__ __forceinline__ void compute_stage(uint32_t sbase, int wm, int wn,
                                                     uint32_t inAtom,
                                                     int acc[4][4][4]) {
    uint32_t abase = sbase + wm * (4 * 512) + inAtom;           // 4 m-atoms
    uint32_t bbase = sbase + STG_A + wn * (2 * 512) + inAtom;   // 2 n-atom-rows
#pragma unroll
    for (int ks = 0; ks < 4; ks++) {                            // 4 k32 atoms
        uint32_t af[4][4], bf[2][4];
#pragma unroll
        for (int am = 0; am < 4; am++) ldm4(af[am], abase + ks * 4096 + am * 512);
#pragma unroll
        for (int bi = 0; bi < 2; bi++) ldm4(bf[bi], bbase + ks * 4096 + bi * 512);
#pragma unroll
        for (int am = 0; am < 4; am++)
#pragma unroll
            for (int ni = 0; ni < 4; ni++)
                mma_s8(acc[am][ni], af[am], bf[ni >> 1][ni & 1],
                       bf[ni >> 1][(ni & 1) + 2]);
    }
}

// Segments: (A1,B1)->accH, (A1,B2)->accM, (A2,B1)->accM.
// LG = log2(128B-chunks per segment); Kseg = 128<<LG bytes; rs = 2*Kseg.
template <int LG>
static __device__ __forceinline__ void gemm_mainloop(const int8_t* gA,
                                                     const int8_t* gB,
                                                     uint32_t sb,
                                                     int accH[4][4][4],
                                                     int accM[4][4][4]) {
    int tid = threadIdx.x, lane = tid & 31, wid = tid >> 5;
    int wm = wid & 1, wn = wid >> 1;
    int quad = lane >> 3;
    int lrow = ((quad & 1) << 3) + (lane & 7);
    int half = quad >> 1;
    uint32_t inAtom = lrow * 32 + ((half ^ ((lrow >> 2) & 1)) << 4);
    const int Kseg = 128 << LG;
    const size_t rs = 2 * (size_t)Kseg;
    const int niter = 3 << LG, cmask = (1 << LG) - 1;

#pragma unroll
    for (int am = 0; am < 4; am++)
#pragma unroll
        for (int ni = 0; ni < 4; ni++)
#pragma unroll
            for (int j = 0; j < 4; j++) { accH[am][ni][j] = 0; accM[am][ni][j] = 0; }

    auto offs = [&](int i, int& kA, int& kB) {
        int s = i >> LG, w = (i & cmask) << 7;
        kA = (s == 2 ? Kseg : 0) + w;
        kB = (s == 1 ? Kseg : 0) + w;
    };

#pragma unroll
    for (int p = 0; p < 3; p++) {
        int a, b; offs(p, a, b);
        load_stage(gA, gB, rs, a, b, sb + p * STG_SZ, tid);
        cpa_commit();
    }

    for (int i = 0; i < niter; i++) {
        if (i < niter - 2)      cpa_wait<2>();
        else if (i == niter - 2) cpa_wait<1>();
        else                     cpa_wait<0>();
        __syncthreads();
        if (i + 3 < niter) {
            int a, b; offs(i + 3, a, b);
            load_stage(gA, gB, rs, a, b, sb + ((i + 3) & 3) * STG_SZ, tid);
            cpa_commit();
        }
        int (*acc)[4][4] = ((i >> LG) == 0) ? accH : accM;
        compute_stage(sb + (i & 3) * STG_SZ, wm, wn, inAtom, acc);
    }
}

// ---------------------------------------------------------------------------
// K-1: global A scale from the analytic LN bound  |xn| <= 5.49*|g| + |b|
// ---------------------------------------------------------------------------
__global__ void scaleA_kernel(const float* __restrict__ gam,
                              const float* __restrict__ bet) {
    int t = threadIdx.x;
    float v = 5.49f * fabsf(gam[t]) + fabsf(bet[t]);
#pragma unroll
    for (int o = 16; o; o >>= 1) v = fmaxf(v, __shfl_xor_sync(0xffffffffu, v, o));
    if (t == 0) {
        v = fmaxf(v, 1e-30f);
        g_SA = v / 127.f;
        g_SAr = 127.f / v;
    }
}

// ---------------------------------------------------------------------------
// K0a: per-column abs-max of the QKV weights, stored at permuted index.
// ---------------------------------------------------------------------------
__global__ void __launch_bounds__(256)
colmax_qkv_kernel(const float* __restrict__ Wq, const float* __restrict__ Wk,
                  const float* __restrict__ Wv) {
    int i = blockIdx.x * 256 + threadIdx.x;
    if (i >= 3 * Ff) return;
    int z = i >> 14, f = i & (Ff - 1);
    const float* W = (z == 0) ? Wq : ((z == 1) ? Wk : Wv);
    float m = 0.f;
    for (int k = 0; k < Kq; k++) m = fmaxf(m, fabsf(W[(size_t)k * Ff + f]));
    m = fmaxf(m, 1e-30f);
    int fp = (f & 7) * 2048 + (f >> 9) * 64 + ((f >> 3) & 63);
    g_sW[z * Ff + fp] = m / 127.f;
    g_sWr[z * Ff + fp] = 127.f / m;
}

__global__ void __launch_bounds__(256)
colmax_wo_kernel(const float* __restrict__ Wo) {
    int f = blockIdx.x * 256 + threadIdx.x;
    if (f >= Nfin) return;
    float m = 0.f;
    for (int k = 0; k < Kf; k++) m = fmaxf(m, fabsf(Wo[(size_t)k * Nfin + f]));
    m = fmaxf(m, 1e-30f);
    int fp = ((f >> 3) & 7) * 256 + (f & 7) * 32 + (f >> 6);
    g_sWo[fp] = m / 127.f;
    g_sWor[fp] = 127.f / m;
}

// ---------------------------------------------------------------------------
// K0b: transpose + two-level int8 quantize with column permutation.
//   src fp32 [R][C] -> dst s8 [C][2R] = [lvl1 | lvl2], dst row = perm(n).
// ---------------------------------------------------------------------------
__global__ void __launch_bounds__(256)
transpose_quant_kernel(const float* __restrict__ src, int8_t* __restrict__ dst,
                       const float* __restrict__ recips, int R, int C, int mode) {
    __shared__ float t[32][33];
    int tx = threadIdx.x, ty = threadIdx.y;
    int c0 = blockIdx.x * 32, r0 = blockIdx.y * 32;
#pragma unroll
    for (int i = 0; i < 4; i++)
        t[ty + i * 8][tx] = src[(size_t)(r0 + ty + i * 8) * C + c0 + tx];
    __syncthreads();
#pragma unroll
    for (int i = 0; i < 4; i++) {
        float v = t[tx][ty + i * 8];
        int n = c0 + ty + i * 8;
        int np = (mode == 0)
               ? ((n & 7) * 2048 + (n >> 9) * 64 + ((n >> 3) & 63))
               : (((n >> 3) & 7) * 256 + (n & 7) * 32 + (n >> 6));
        float q = v * recips[np];
        int q1 = __float2int_rn(q);
        int q2 = __float2int_rn((q - (float)q1) * 128.f);
        size_t base = (size_t)np * (2 * R) + r0 + tx;
        dst[base]     = (int8_t)q1;
        dst[base + R] = (int8_t)q2;
    }
}

// Permute biases into the same column orders.
__global__ void __launch_bounds__(256)
perm_bias_kernel(const float* __restrict__ bq, const float* __restrict__ bk,
                 const float* __restrict__ bv, const float* __restrict__ bo) {
    int i = blockIdx.x * 256 + threadIdx.x;
    if (i < 3 * Ff) {
        int z = i >> 14, f = i & (Ff - 1);
        const float* s = (z == 0) ? bq : ((z == 1) ? bk : bv);
        int fp = (f & 7) * 2048 + (f >> 9) * 64 + ((f >> 3) & 63);
        g_bP[z * Ff + fp] = s[f];
    } else if (i < 3 * Ff + Nfin) {
        int f = i - 3 * Ff;
        int fp = ((f >> 3) & 7) * 256 + (f & 7) * 32 + (f >> 6);
        g_bP[3 * Ff + fp] = bo[f];
    }
}

// ---------------------------------------------------------------------------
// K1: LN over C=32 per pixel + im2col -> A8 two-level int8 (global scale).
// ---------------------------------------------------------------------------
__global__ void ln_im2col_kernel(const float* __restrict__ x,
                                 const float* __restrict__ gam,
                                 const float* __restrict__ bet) {
    int pix  = (blockIdx.x * blockDim.x + threadIdx.x) >> 5;
    int lane = threadIdx.x & 31;
    if (pix >= Bb * Hh * Ww) return;

    float v = x[(size_t)pix * Cc + lane];
    float mu = v;
#pragma unroll
    for (int o = 16; o; o >>= 1) mu += __shfl_xor_sync(0xffffffffu, mu, o);
    mu *= (1.0f / 32.0f);
    float d = v - mu;
    float var = d * d;
#pragma unroll
    for (int o = 16; o; o >>= 1) var += __shfl_xor_sync(0xffffffffu, var, o);
    var *= (1.0f / 32.0f);
    float xn = d * rsqrtf(var + 1e-6f) * gam[lane] + bet[lane];

    int w = pix % Ww;
    int h = (pix / Ww) % Hh;
    int b = pix / (Ww * Hh);
    int m = b * 1024 + (h >> 3) * 32 + (w >> 3);
    int k = (h & 7) * 256 + (w & 7) * 32 + lane;
    float q = xn * g_SAr;
    int q1 = __float2int_rn(q);
    int q2 = __float2int_rn((q - (float)q1) * 128.f);
    size_t o = (size_t)m * (2 * Kq) + k;
    g_A8[o]      = (int8_t)q1;
    g_A8[o + Kq] = (int8_t)q2;
}

// ---------------------------------------------------------------------------
// K2: Q/K/V GEMM (int8). grid (16, 128, 3); col-major raster for L2 reuse.
// Output columns permuted: f' = head*2048 + c*64 + pos.
// ---------------------------------------------------------------------------
__global__ void __launch_bounds__(256, 1)
gemm_qkv_kernel() {
    extern __shared__ char smem[];
    uint32_t sb = s2u(smem);
    int tid = threadIdx.x, lane = tid & 31, wid = tid >> 5;
    int wm = wid & 1, wn = wid >> 1;
    int bm = blockIdx.x * 128, bn = blockIdx.y * 128, z = blockIdx.z;

    const int8_t* gA = g_A8 + (size_t)bm * (2 * Kq);
    const int8_t* gB = g_W8 + ((size_t)z * Ff + bn) * (2 * Kq);

    int accH[4][4][4], accM[4][4][4];
    gemm_mainloop<4>(gA, gB, sb, accH, accM);

    const float SA = g_SA;
    float* Cg = g_QKV + (size_t)z * Mm * Ff;
    const float* bias = g_bP + z * Ff;
    const float* sW = g_sW + z * Ff;
    int g = lane >> 2, t = lane & 3;
#pragma unroll
    for (int am = 0; am < 4; am++)
#pragma unroll
        for (int rr = 0; rr < 2; rr++) {
            int row = bm + wm * 64 + am * 16 + rr * 8 + g;
            float* crow = Cg + (size_t)row * Ff;
#pragma unroll
            for (int ni = 0; ni < 4; ni++) {
                int fp = bn + wn * 32 + ni * 8 + t * 2;
                float s0 = SA * sW[fp], s1 = SA * sW[fp + 1];
                float2 bi2 = *(const float2*)(bias + fp);
                float v0 = (float)accH[am][ni][rr * 2 + 0]
                         + 0.0078125f * (float)accM[am][ni][rr * 2 + 0];
                float v1 = (float)accH[am][ni][rr * 2 + 1]
                         + 0.0078125f * (float)accM[am][ni][rr * 2 + 1];
                float2 o;
                o.x = s0 * v0 + bi2.x;
                o.y = s1 * v1 + bi2.y;
                *(float2*)(crow + fp) = o;
            }
        }
}

// ---------------------------------------------------------------------------
// K3: attention, one CTA per patch m (all 8 heads): circular conv + LN +
// gate, stash o[16384] in smem, row-max, two-level int8 quantize -> O8.
// ---------------------------------------------------------------------------
#define ASMEM 101120

__global__ void __launch_bounds__(256)
attn_kernel(const float* __restrict__ l2s, const float* __restrict__ l2b) {
    extern __shared__ float sm[];
    float* stash = sm;                  // 16384
    float* qs    = sm + 16384;          // 2048
    float* ks    = qs + 2048;           // 2048
    float* vs    = ks + 2048;           // [32][68]
    float* outs  = vs + 2176;           // [32][68]
    float* s2    = outs + 2176;         // 32
    float* b2    = s2 + 32;             // 32
    float* mus   = b2 + 32;             // 64
    float* rstds = mus + 64;            // 64
    float* red   = rstds + 64;          // 256

    int m = blockIdx.x;
    int tid = threadIdx.x;

    const float* Qm = g_QKV + (size_t)m * Ff;
    const float* Km = Qm + (size_t)Mm * Ff;
    const float* Vm = Qm + (size_t)2 * Mm * Ff;

    if (tid < 32) { s2[tid] = l2s[tid]; b2[tid] = l2b[tid]; }
    float lmax = 0.f;

    for (int h = 0; h < HEADS; h++) {
        __syncthreads();
        const float* Q = Qm + h * 2048;
        const float* Kp = Km + h * 2048;
        const float* V = Vm + h * 2048;
#pragma unroll
        for (int it = 0; it < 2; it++) {
            int i4 = it * 256 + tid;
            float4 qv = ((const float4*)Q)[i4];
            float4 kv = ((const float4*)Kp)[i4];
            float4 vv = ((const float4*)V)[i4];
            int idx = i4 * 4;
            *(float4*)&qs[idx] = qv;
            *(float4*)&ks[idx] = kv;
            int c = idx >> 6, pos = idx & 63;
            *(float4*)&vs[c * 68 + pos] = vv;
        }
        __syncthreads();

        float res[8];
#pragma unroll
        for (int j = 0; j < 8; j++) {
            int idx = j * 256 + tid;
            int c = idx >> 6, pos = idx & 63;
            int s = pos >> 3, t = pos & 7;
            const float* qc = &qs[c * 64];
            const float* kc = &ks[c * 64];
            float sum = 0.f;
#pragma unroll
            for (int u = 0; u < 8; u++) {
                int su = ((s - u) & 7) * 8;
#pragma unroll
                for (int v = 0; v < 8; v++)
                    sum += qc[u * 8 + v] * kc[su + ((t - v) & 7)];
            }
            res[j] = sum;
        }
#pragma unroll
        for (int j = 0; j < 8; j++) {
            int idx = j * 256 + tid;
            int c = idx >> 6, pos = idx & 63;
            outs[c * 68 + pos] = res[j];
        }
        __syncthreads();

        if (tid < 64) {
            float mu = 0.f;
#pragma unroll
            for (int c = 0; c < 32; c++) mu += outs[c * 68 + tid];
            mu *= (1.0f / 32.0f);
            float var = 0.f;
#pragma unroll
            for (int c = 0; c < 32; c++) {
                float d = outs[c * 68 + tid] - mu;
                var += d * d;
            }
            var *= (1.0f / 32.0f);
            mus[tid] = mu;
            rstds[tid] = rsqrtf(var + 1e-6f);
        }
        __syncthreads();

#pragma unroll
        for (int it = 0; it < 8; it++) {
            int idx = it * 256 + tid;
            int c = idx & 31, pos = idx >> 5;
            int p0 = pos >> 3, p1 = pos & 7;
            float val = (outs[c * 68 + pos] - mus[pos]) * rstds[pos] * s2[c] + b2[c];
            float prod = vs[c * 68 + pos] * val;
            stash[p0 * 2048 + p1 * 256 + h * 32 + c] = prod;
            lmax = fmaxf(lmax, fabsf(prod));
        }
    }

    red[tid] = lmax;
    __syncthreads();
    for (int s = 128; s > 0; s >>= 1) {
        if (tid < s) red[tid] = fmaxf(red[tid], red[tid + s]);
        __syncthreads();
    }
    if (tid == 0) {
        float mx = fmaxf(red[0], 1e-30f);
        g_sO[m] = mx / 127.f;
        red[0] = 127.f / mx;
    }
    __syncthreads();
    float inv = red[0];

    size_t Obase = (size_t)m * (2 * Kf);
#pragma unroll
    for (int it = 0; it < 64; it++) {
        int k = it * 256 + tid;
        float q = stash[k] * inv;
        int q1 = __float2int_rn(q);
        int q2 = __float2int_rn((q - (float)q1) * 128.f);
        g_O8[Obase + k]      = (int8_t)q1;
        g_O8[Obase + Kf + k] = (int8_t)q2;
    }
}

// ---------------------------------------------------------------------------
// K4: output GEMM (int8) + scatter + residual.  grid (16, 16).
// Output columns permuted: f2' = p0*256 + p1*32 + c  -> coalesced scatter.
// ---------------------------------------------------------------------------
__global__ void __launch_bounds__(256, 1)
gemm_out_kernel(const float* __restrict__ xin, float* __restrict__ out) {
    extern __shared__ char smem[];
    uint32_t sb = s2u(smem);
    int tid = threadIdx.x, lane = tid & 31, wid = tid >> 5;
    int wm = wid & 1, wn = wid >> 1;
    int bm = blockIdx.x * 128, bn = blockIdx.y * 128;

    const int8_t* gA = g_O8 + (size_t)bm * (2 * Kf);
    const int8_t* gB = g_Wo8 + (size_t)bn * (2 * Kf);

    int accH[4][4][4], accM[4][4][4];
    gemm_mainloop<7>(gA, gB, sb, accH, accM);

    const float* bias = g_bP + 3 * Ff;
    int g = lane >> 2, t = lane & 3;
#pragma unroll
    for (int am = 0; am < 4; am++)
#pragma unroll
        for (int rr = 0; rr < 2; rr++) {
            int row = bm + wm * 64 + am * 16 + rr * 8 + g;
            int b_ = row >> 10, gh = (row >> 5) & 31, gw = row & 31;
            float sR = g_sO[row];
#pragma unroll
            for (int ni = 0; ni < 4; ni++) {
                int fp = bn + wn * 32 + ni * 8 + t * 2;
                int c = fp & 31, p1 = (fp >> 5) & 7, p0 = (fp >> 8) & 7;
                size_t oi = (((size_t)(b_ * Hh + gh * 8 + p0)) * Ww
                             + gw * 8 + p1) * Cc + c;
                float s0 = sR * g_sWo[fp], s1 = sR * g_sWo[fp + 1];
                float v0 = (float)accH[am][ni][rr * 2 + 0]
                         + 0.0078125f * (float)accM[am][ni][rr * 2 + 0];
                float v1 = (float)accH[am][ni][rr * 2 + 1]
                         + 0.0078125f * (float)accM[am][ni][rr * 2 + 1];
                float2 xi = *(const float2*)(xin + oi);
                float2 bi2 = *(const float2*)(bias + fp);
                float2 o;
                o.x = s0 * v0 + bi2.x + xi.x;
                o.y = s1 * v1 + bi2.y + xi.y;
                *(float2*)(out + oi) = o;
            }
        }
}

// ---------------------------------------------------------------------------
extern "C" void kernel_launch(void* const* d_in, const int* in_sizes, int n_in,
                              void* d_out, int out_size) {
    const float* x   = (const float*)d_in[0];
    const float* l1s = (const float*)d_in[1];
    const float* l1b = (const float*)d_in[2];
    const float* Wq  = (const float*)d_in[3];
    const float* bq  = (const float*)d_in[4];
    const float* Wk  = (const float*)d_in[5];
    const float* bk  = (const float*)d_in[6];
    const float* Wv  = (const float*)d_in[7];
    const float* bv  = (const float*)d_in[8];
    const float* l2s = (const float*)d_in[9];
    const float* l2b = (const float*)d_in[10];
    const float* Wo  = (const float*)d_in[11];
    const float* bo  = (const float*)d_in[12];
    float* out = (float*)d_out;

    cudaFuncSetAttribute(gemm_qkv_kernel,
                         cudaFuncAttributeMaxDynamicSharedMemorySize, GSMEM);
    cudaFuncSetAttribute(gemm_out_kernel,
                         cudaFuncAttributeMaxDynamicSharedMemorySize, GSMEM);
    cudaFuncSetAttribute(attn_kernel,
                         cudaFuncAttributeMaxDynamicSharedMemorySize, ASMEM);

    void *w8, *wo8, *swr, *swor;
    cudaGetSymbolAddress(&w8, g_W8);
    cudaGetSymbolAddress(&wo8, g_Wo8);
    cudaGetSymbolAddress(&swr, g_sWr);
    cudaGetSymbolAddress(&swor, g_sWor);

    // scales
    scaleA_kernel<<<1, 32>>>(l1s, l1b);
    colmax_qkv_kernel<<<(3 * Ff) / 256, 256>>>(Wq, Wk, Wv);
    colmax_wo_kernel<<<Nfin / 256, 256>>>(Wo);

    // transpose + quantize weights
    dim3 tb(32, 8);
    const size_t WSZ = (size_t)Ff * 2 * Kq;
    transpose_quant_kernel<<<dim3(512, 64), tb>>>(Wq, (int8_t*)w8,
                                                  (const float*)swr, Kq, Ff, 0);
    transpose_quant_kernel<<<dim3(512, 64), tb>>>(Wk, (int8_t*)w8 + WSZ,
                                                  (const float*)swr + Ff, Kq, Ff, 0);
    transpose_quant_kernel<<<dim3(512, 64), tb>>>(Wv, (int8_t*)w8 + 2 * WSZ,
                                                  (const float*)swr + 2 * Ff, Kq, Ff, 0);
    transpose_quant_kernel<<<dim3(64, 512), tb>>>(Wo, (int8_t*)wo8,
                                                  (const float*)swor, Kf, Nfin, 1);

    perm_bias_kernel<<<(3 * Ff + Nfin + 255) / 256, 256>>>(bq, bk, bv, bo);

    ln_im2col_kernel<<<(Bb * Hh * Ww * 32) / 256, 256>>>(x, l1s, l1b);

    dim3 gq(16, 128, 3);
    gemm_qkv_kernel<<<gq, 256, GSMEM>>>();

    attn_kernel<<<Mm, 256, ASMEM>>>(l2s, l2b);

    dim3 go(16, 16);
    gemm_out_kernel<<<go, 256, GSMEM>>>(x, out);
}

// round 10
// speedup vs baseline: 4.9544x; 4.9544x over previous
#include <cuda_runtime.h>
#include <cuda_fp16.h>
#include <cstdint>

// ---------------------------------------------------------------------------
// ImageFusion via mma.sync fp16 GEMMs, 2-term activation-exact split:
//   A = Ah + Al (both fp16, exact);  B ~= Bh = fp16(B)
//   A@B ~= Ah@Bh + Al@Bh          (only error: fp16 rounding of weights)
// The k-loop walks 2*(K/64) chunks interleaved (hi,lo) so each B chunk is
// loaded twice back-to-back (second is an L2 hit).
// Base-ISA only (ptxas targets sm_103 without 'a' features).
// ---------------------------------------------------------------------------

#define Bb    2
#define Hh    256
#define Ww    256
#define Cc    32
#define HEADS 8
#define Mm    2048
#define Kq    2048
#define Ff    16384
#define Kf    16384
#define Nfin  2048

// ---- scratch ----
__device__ __align__(1024) __half g_A2[(size_t)Mm * 2 * Kq];       //  16 MB
__device__ __align__(1024) __half g_W2[(size_t)3 * Ff * Kq];       // 201 MB
__device__ __align__(1024) __half g_Wo2[(size_t)Nfin * Kf];        //  67 MB
__device__ float                  g_QKV[(size_t)3 * Mm * Ff];      // 402 MB
__device__ __align__(1024) __half g_O2[(size_t)Mm * 2 * Kf];       // 134 MB
__device__ float                  g_bP[3 * Ff + Nfin];             // permuted biases

// ---------------------------------------------------------------------------
// helpers
// ---------------------------------------------------------------------------
static __device__ __forceinline__ uint32_t s2u(const void* p) {
    uint32_t a;
    asm("{ .reg .u64 t; cvta.to.shared.u64 t, %1; cvt.u32.u64 %0, t; }"
        : "=r"(a) : "l"(p));
    return a;
}
static __device__ __forceinline__ void cpa16(uint32_t dst, const void* src) {
    asm volatile("cp.async.cg.shared.global [%0], [%1], 16;\n"
                 :: "r"(dst), "l"(src));
}
static __device__ __forceinline__ void cpa_commit() {
    asm volatile("cp.async.commit_group;\n");
}
template <int N>
static __device__ __forceinline__ void cpa_wait() {
    asm volatile("cp.async.wait_group %0;\n" :: "n"(N));
}
static __device__ __forceinline__ void ldm4(uint32_t* r, uint32_t a) {
    asm volatile("ldmatrix.sync.aligned.m8n8.x4.shared.b16 {%0,%1,%2,%3}, [%4];"
                 : "=r"(r[0]), "=r"(r[1]), "=r"(r[2]), "=r"(r[3]) : "r"(a));
}
static __device__ __forceinline__ void mma16816(float* d, const uint32_t* a,
                                                uint32_t b0, uint32_t b1) {
    asm volatile("mma.sync.aligned.m16n8k16.row.col.f32.f16.f16.f32 "
                 "{%0,%1,%2,%3}, {%4,%5,%6,%7}, {%8,%9}, {%0,%1,%2,%3};"
                 : "+f"(d[0]), "+f"(d[1]), "+f"(d[2]), "+f"(d[3])
                 : "r"(a[0]), "r"(a[1]), "r"(a[2]), "r"(a[3]), "r"(b0), "r"(b1));
}

// ---------------------------------------------------------------------------
// GEMM core: BM=128, BN=128, BK=64, 128 threads (4 warps 2x2, warp 64x64),
// 3-stage cp.async pipeline.  SMEM: 16x16 fp16 atoms (512B), atom (ka,i) at
// (ka*8+i)*512; element (row,col) at row*32 + ((col>>3 ^ (row>>2)&1)<<4)
// + (col&7)*2 — conflict-free for both cp.async stores and ldmatrix.
// ---------------------------------------------------------------------------
#define STG_A   16384
#define STG_SZ  32768
#define GSMEM   (3 * STG_SZ)

static __device__ __forceinline__ void load_stage(const __half* gA,
                                                  const __half* gB,
                                                  size_t rsA, size_t rsB,
                                                  int kA, int kB,
                                                  uint32_t base, int tid) {
#pragma unroll
    for (int it = 0; it < 8; it++) {           // A: 128 rows x 8 16B-chunks
        int q = it * 128 + tid;
        int m = q >> 3, h2 = q & 7;
        uint32_t dst = base + ((h2 >> 1) * 8 + (m >> 4)) * 512 + (m & 15) * 32
                     + (((h2 & 1) ^ ((m >> 2) & 1)) << 4);
        cpa16(dst, gA + (size_t)m * rsA + kA + (h2 << 3));
    }
#pragma unroll
    for (int it = 0; it < 8; it++) {           // B: 128 rows x 8 16B-chunks
        int q = it * 128 + tid;
        int n = q >> 3, h2 = q & 7;
        uint32_t dst = base + STG_A + ((h2 >> 1) * 8 + (n >> 4)) * 512
                     + (n & 15) * 32 + (((h2 & 1) ^ ((n >> 2) & 1)) << 4);
        cpa16(dst, gB + (size_t)n * rsB + kB + (h2 << 3));
    }
}

static __device__ __forceinline__ void compute_stage(uint32_t sbase, int wm, int wn,
                                                     uint32_t inAtom,
                                                     float acc[4][8][4]) {
    uint32_t abase = sbase + wm * (4 * 512) + inAtom;          // 4 m-atoms/warp
    uint32_t bbase = sbase + STG_A + wn * (4 * 512) + inAtom;  // 4 n-atoms/warp
#pragma unroll
    for (int ks = 0; ks < 4; ks++) {
        uint32_t af[4][4], bf[4][4];
#pragma unroll
        for (int am = 0; am < 4; am++) ldm4(af[am], abase + ks * 4096 + am * 512);
#pragma unroll
        for (int bi = 0; bi < 4; bi++) ldm4(bf[bi], bbase + ks * 4096 + bi * 512);
#pragma unroll
        for (int am = 0; am < 4; am++)
#pragma unroll
            for (int bi = 0; bi < 4; bi++) {
                mma16816(acc[am][bi * 2 + 0], af[am], bf[bi][0], bf[bi][2]);
                mma16816(acc[am][bi * 2 + 1], af[am], bf[bi][1], bf[bi][3]);
            }
    }
}

// 2 segments interleaved per chunk: i even -> (Ah, B), i odd -> (Al, B).
// LG = log2(chunks); Kseg = 64<<LG; A rows are [hi|lo] (2*Kseg), B rows Kseg.
template <int LG>
static __device__ __forceinline__ void gemm_mainloop(const __half* gA,
                                                     const __half* gB,
                                                     uint32_t sb,
                                                     float acc[4][8][4]) {
    int tid = threadIdx.x, lane = tid & 31, wid = tid >> 5;
    int wm = wid & 1, wn = wid >> 1;
    int quad = lane >> 3;
    int lrow = ((quad & 1) << 3) + (lane & 7);
    int half = quad >> 1;
    uint32_t inAtom = lrow * 32 + ((half ^ ((lrow >> 2) & 1)) << 4);
    const int Kseg = 64 << LG;
    const size_t rsA = 2 * (size_t)Kseg, rsB = (size_t)Kseg;
    const int niter = 2 << LG;

#pragma unroll
    for (int am = 0; am < 4; am++)
#pragma unroll
        for (int ni = 0; ni < 8; ni++)
#pragma unroll
            for (int j = 0; j < 4; j++) acc[am][ni][j] = 0.f;

    auto offs = [&](int i, int& kA, int& kB) {
        int w = (i >> 1) << 6;
        kA = ((i & 1) ? Kseg : 0) + w;
        kB = w;
    };

    { int a, b; offs(0, a, b); load_stage(gA, gB, rsA, rsB, a, b, sb, tid); }
    cpa_commit();
    { int a, b; offs(1, a, b); load_stage(gA, gB, rsA, rsB, a, b, sb + STG_SZ, tid); }
    cpa_commit();

    int st = 0, st2 = 2;
    for (int i = 0; i < niter; i++) {
        if (i + 1 < niter) cpa_wait<1>(); else cpa_wait<0>();
        __syncthreads();
        if (i + 2 < niter) {
            int a, b; offs(i + 2, a, b);
            load_stage(gA, gB, rsA, rsB, a, b, sb + st2 * STG_SZ, tid);
            cpa_commit();
        }
        compute_stage(sb + st * STG_SZ, wm, wn, inAtom, acc);
        st = (st == 2) ? 0 : st + 1;
        st2 = (st2 == 2) ? 0 : st2 + 1;
    }
}

// ---------------------------------------------------------------------------
// K0: transpose to fp16 with column permutation.
//   src fp32 [R][C] -> dst fp16 [C][R], dst row = perm(n).
//   mode 0 (QKV):  n = c*512+p0*64+p1*8+head -> n' = head*2048 + c*64 + pos
//   mode 1 (Wo):   n = c*64+p0*8+p1          -> n' = p0*256 + p1*32 + c
// ---------------------------------------------------------------------------
__global__ void __launch_bounds__(256)
transpose_half_kernel(const float* __restrict__ src,
                      __half* __restrict__ dst, int R, int C, int mode) {
    __shared__ float t[32][33];
    int tx = threadIdx.x, ty = threadIdx.y;
    int c0 = blockIdx.x * 32, r0 = blockIdx.y * 32;
#pragma unroll
    for (int i = 0; i < 4; i++)
        t[ty + i * 8][tx] = src[(size_t)(r0 + ty + i * 8) * C + c0 + tx];
    __syncthreads();
#pragma unroll
    for (int i = 0; i < 4; i++) {
        float v = t[tx][ty + i * 8];
        int n = c0 + ty + i * 8;
        int np = (mode == 0)
               ? ((n & 7) * 2048 + (n >> 9) * 64 + ((n >> 3) & 63))
               : (((n >> 3) & 7) * 256 + (n & 7) * 32 + (n >> 6));
        dst[(size_t)np * R + r0 + tx] = __float2half_rn(v);
    }
}

// Permute biases into the same column orders.
__global__ void __launch_bounds__(256)
perm_bias_kernel(const float* __restrict__ bq, const float* __restrict__ bk,
                 const float* __restrict__ bv, const float* __restrict__ bo) {
    int i = blockIdx.x * 256 + threadIdx.x;
    if (i < 3 * Ff) {
        int z = i >> 14, f = i & (Ff - 1);
        const float* s = (z == 0) ? bq : ((z == 1) ? bk : bv);
        int fp = (f & 7) * 2048 + (f >> 9) * 64 + ((f >> 3) & 63);
        g_bP[z * Ff + fp] = s[f];
    } else if (i < 3 * Ff + Nfin) {
        int f = i - 3 * Ff;
        int fp = ((f >> 3) & 7) * 256 + (f & 7) * 32 + (f >> 6);
        g_bP[3 * Ff + fp] = bo[f];
    }
}

// ---------------------------------------------------------------------------
// K1: LN over C=32 per pixel + im2col -> A2 [hi | lo] fp16 (exact split).
// ---------------------------------------------------------------------------
__global__ void ln_im2col_kernel(const float* __restrict__ x,
                                 const float* __restrict__ gam,
                                 const float* __restrict__ bet) {
    int pix  = (blockIdx.x * blockDim.x + threadIdx.x) >> 5;
    int lane = threadIdx.x & 31;
    if (pix >= Bb * Hh * Ww) return;

    float v = x[(size_t)pix * Cc + lane];
    float mu = v;
#pragma unroll
    for (int o = 16; o; o >>= 1) mu += __shfl_xor_sync(0xffffffffu, mu, o);
    mu *= (1.0f / 32.0f);
    float d = v - mu;
    float var = d * d;
#pragma unroll
    for (int o = 16; o; o >>= 1) var += __shfl_xor_sync(0xffffffffu, var, o);
    var *= (1.0f / 32.0f);
    float xn = d * rsqrtf(var + 1e-6f) * gam[lane] + bet[lane];

    int w = pix % Ww;
    int h = (pix / Ww) % Hh;
    int b = pix / (Ww * Hh);
    int m = b * 1024 + (h >> 3) * 32 + (w >> 3);
    int k = (h & 7) * 256 + (w & 7) * 32 + lane;
    size_t o = (size_t)m * (2 * Kq) + k;
    __half hi = __float2half_rn(xn);
    g_A2[o]      = hi;
    g_A2[o + Kq] = __float2half_rn(xn - __half2float(hi));
}

// ---------------------------------------------------------------------------
// K2: Q/K/V GEMM.  grid (16, 128, 3); column-major raster -> B-tile L2 reuse.
// Output columns are permuted: f' = head*2048 + c*64 + pos.
// ---------------------------------------------------------------------------
__global__ void __launch_bounds__(128, 2)
gemm_qkv_kernel() {
    extern __shared__ char smem[];
    uint32_t sb = s2u(smem);
    int tid = threadIdx.x, lane = tid & 31, wid = tid >> 5;
    int wm = wid & 1, wn = wid >> 1;
    int bm = blockIdx.x * 128, bn = blockIdx.y * 128, z = blockIdx.z;

    const __half* gA = g_A2 + (size_t)bm * (2 * Kq);
    const __half* gB = g_W2 + ((size_t)z * Ff + bn) * Kq;

    float acc[4][8][4];
    gemm_mainloop<5>(gA, gB, sb, acc);

    float* Cg = g_QKV + (size_t)z * Mm * Ff;
    const float* bias = g_bP + z * Ff;
    int g = lane >> 2, t = lane & 3;
#pragma unroll
    for (int am = 0; am < 4; am++)
#pragma unroll
        for (int rr = 0; rr < 2; rr++) {
            int row = bm + wm * 64 + am * 16 + rr * 8 + g;
            float* crow = Cg + (size_t)row * Ff;
#pragma unroll
            for (int ni = 0; ni < 8; ni++) {
                int fp = bn + wn * 64 + ni * 8 + t * 2;
                float2 bi2 = *(const float2*)(bias + fp);
                float2 o;
                o.x = acc[am][ni][rr * 2 + 0] + bi2.x;
                o.y = acc[am][ni][rr * 2 + 1] + bi2.y;
                *(float2*)(crow + fp) = o;
            }
        }
}

// ---------------------------------------------------------------------------
// K3: attention (8x8 circular conv) + LN + gate -> O2 [hi | lo] fp16.
// QKV layout is head-major: Q[m][head*2048 + c*64 + pos] (coalesced).
// ---------------------------------------------------------------------------
__global__ void __launch_bounds__(256)
attn_kernel(const float* __restrict__ l2s, const float* __restrict__ l2b) {
    __shared__ float qs[32 * 64];
    __shared__ float ks[32 * 64];
    __shared__ float vs[32 * 68];
    __shared__ float outs[32 * 68];
    __shared__ float s2[32], b2[32], mus[64], rstds[64];

    int m = blockIdx.x;
    int head = blockIdx.y;
    int tid = threadIdx.x;

    const float* Q  = g_QKV + (size_t)m * Ff + head * 2048;
    const float* Kp = Q + (size_t)Mm * Ff;
    const float* V  = Q + (size_t)2 * Mm * Ff;

    if (tid < 32) { s2[tid] = l2s[tid]; b2[tid] = l2b[tid]; }

#pragma unroll
    for (int it = 0; it < 2; it++) {
        int i4 = it * 256 + tid;
        float4 qv = ((const float4*)Q)[i4];
        float4 kv = ((const float4*)Kp)[i4];
        float4 vv = ((const float4*)V)[i4];
        int idx = i4 * 4;
        *(float4*)&qs[idx] = qv;
        *(float4*)&ks[idx] = kv;
        int c = idx >> 6, pos = idx & 63;
        *(float4*)&vs[c * 68 + pos] = vv;
    }
    __syncthreads();

    float res[8];
#pragma unroll
    for (int j = 0; j < 8; j++) {
        int idx = j * 256 + tid;
        int c = idx >> 6, pos = idx & 63;
        int s = pos >> 3, t = pos & 7;
        const float* qc = &qs[c * 64];
        const float* kc = &ks[c * 64];
        float sum = 0.f;
#pragma unroll
        for (int u = 0; u < 8; u++) {
            int su = ((s - u) & 7) * 8;
#pragma unroll
            for (int v = 0; v < 8; v++)
                sum += qc[u * 8 + v] * kc[su + ((t - v) & 7)];
        }
        res[j] = sum;
    }
#pragma unroll
    for (int j = 0; j < 8; j++) {
        int idx = j * 256 + tid;
        int c = idx >> 6, pos = idx & 63;
        outs[c * 68 + pos] = res[j];
    }
    __syncthreads();

    if (tid < 64) {
        float mu = 0.f;
#pragma unroll
        for (int c = 0; c < 32; c++) mu += outs[c * 68 + tid];
        mu *= (1.0f / 32.0f);
        float var = 0.f;
#pragma unroll
        for (int c = 0; c < 32; c++) {
            float d = outs[c * 68 + tid] - mu;
            var += d * d;
        }
        var *= (1.0f / 32.0f);
        mus[tid] = mu;
        rstds[tid] = rsqrtf(var + 1e-6f);
    }
    __syncthreads();

    size_t Obase = (size_t)m * (2 * Kf);
#pragma unroll
    for (int it = 0; it < 8; it++) {
        int idx = it * 256 + tid;
        int c = idx & 31, pos = idx >> 5;
        int p0 = pos >> 3, p1 = pos & 7;
        float val = (outs[c * 68 + pos] - mus[pos]) * rstds[pos] * s2[c] + b2[c];
        float prod = vs[c * 68 + pos] * val;
        size_t o = Obase + p0 * 2048 + p1 * 256 + head * 32 + c;
        __half h = __float2half_rn(prod);
        g_O2[o]      = h;
        g_O2[o + Kf] = __float2half_rn(prod - __half2float(h));
    }
}

// ---------------------------------------------------------------------------
// K4: output GEMM + scatter + residual.  grid (16, 16).
// Output columns permuted: f2' = p0*256 + p1*32 + c  -> coalesced scatter.
// ---------------------------------------------------------------------------
__global__ void __launch_bounds__(128, 2)
gemm_out_kernel(const float* __restrict__ xin, float* __restrict__ out) {
    extern __shared__ char smem[];
    uint32_t sb = s2u(smem);
    int tid = threadIdx.x, lane = tid & 31, wid = tid >> 5;
    int wm = wid & 1, wn = wid >> 1;
    int bm = blockIdx.x * 128, bn = blockIdx.y * 128;

    const __half* gA = g_O2 + (size_t)bm * (2 * Kf);
    const __half* gB = g_Wo2 + (size_t)bn * Kf;

    float acc[4][8][4];
    gemm_mainloop<8>(gA, gB, sb, acc);

    const float* bias = g_bP + 3 * Ff;
    int g = lane >> 2, t = lane & 3;
#pragma unroll
    for (int am = 0; am < 4; am++)
#pragma unroll
        for (int rr = 0; rr < 2; rr++) {
            int row = bm + wm * 64 + am * 16 + rr * 8 + g;
            int b_ = row >> 10, gh = (row >> 5) & 31, gw = row & 31;
#pragma unroll
            for (int ni = 0; ni < 8; ni++) {
                int fp = bn + wn * 64 + ni * 8 + t * 2;
                int c = fp & 31, p1 = (fp >> 5) & 7, p0 = (fp >> 8) & 7;
                size_t oi = (((size_t)(b_ * Hh + gh * 8 + p0)) * Ww
                             + gw * 8 + p1) * Cc + c;
                float2 xi = *(const float2*)(xin + oi);
                float2 bi2 = *(const float2*)(bias + fp);
                float2 o;
                o.x = acc[am][ni][rr * 2 + 0] + bi2.x + xi.x;
                o.y = acc[am][ni][rr * 2 + 1] + bi2.y + xi.y;
                *(float2*)(out + oi) = o;
            }
        }
}

// ---------------------------------------------------------------------------
extern "C" void kernel_launch(void* const* d_in, const int* in_sizes, int n_in,
                              void* d_out, int out_size) {
    const float* x   = (const float*)d_in[0];
    const float* l1s = (const float*)d_in[1];
    const float* l1b = (const float*)d_in[2];
    const float* Wq  = (const float*)d_in[3];
    const float* bq  = (const float*)d_in[4];
    const float* Wk  = (const float*)d_in[5];
    const float* bk  = (const float*)d_in[6];
    const float* Wv  = (const float*)d_in[7];
    const float* bv  = (const float*)d_in[8];
    const float* l2s = (const float*)d_in[9];
    const float* l2b = (const float*)d_in[10];
    const float* Wo  = (const float*)d_in[11];
    const float* bo  = (const float*)d_in[12];
    float* out = (float*)d_out;

    cudaFuncSetAttribute(gemm_qkv_kernel,
                         cudaFuncAttributeMaxDynamicSharedMemorySize, GSMEM);
    cudaFuncSetAttribute(gemm_out_kernel,
                         cudaFuncAttributeMaxDynamicSharedMemorySize, GSMEM);

    void *w2, *wo2;
    cudaGetSymbolAddress(&w2, g_W2);
    cudaGetSymbolAddress(&wo2, g_Wo2);

    dim3 tb(32, 8);
    const size_t WSZ = (size_t)Ff * Kq;
    transpose_half_kernel<<<dim3(512, 64), tb>>>(Wq, (__half*)w2, Kq, Ff, 0);
    transpose_half_kernel<<<dim3(512, 64), tb>>>(Wk, (__half*)w2 + WSZ, Kq, Ff, 0);
    transpose_half_kernel<<<dim3(512, 64), tb>>>(Wv, (__half*)w2 + 2 * WSZ, Kq, Ff, 0);
    transpose_half_kernel<<<dim3(64, 512), tb>>>(Wo, (__half*)wo2, Kf, Nfin, 1);

    perm_bias_kernel<<<(3 * Ff + Nfin + 255) / 256, 256>>>(bq, bk, bv, bo);

    ln_im2col_kernel<<<(Bb * Hh * Ww * 32) / 256, 256>>>(x, l1s, l1b);

    dim3 gq(16, 128, 3);
    gemm_qkv_kernel<<<gq, 128, GSMEM>>>();

    dim3 ga(Mm, HEADS);
    attn_kernel<<<ga, 256>>>(l2s, l2b);

    dim3 go(16, 16);
    gemm_out_kernel<<<go, 128, GSMEM>>>(x, out);
}

// round 11
// speedup vs baseline: 8.5361x; 1.7229x over previous
#include <cuda_runtime.h>
#include <cuda_fp16.h>
#include <cstdint>

// ---------------------------------------------------------------------------
// ImageFusion via single-pass fp16 mma.sync GEMMs (minimum-FLOP form).
// All four GEMMs run one fp16 pass; error sources are 4 weight roundings +
// A/O activation roundings, measured-budget ~5.5e-4 << 1e-3 threshold.
// Base-ISA only (ptxas targets sm_103 without 'a' features).
//   K0 transpose_half : W[K][N] fp32 -> W[N][K] fp16 (columns permuted)
//   K1 ln_im2col      : LN(x) -> A[2048][2048] fp16
//   K2 gemm_qkv       : QKV fp32 = A @ W^T + b        (mma.sync fp16)
//   K3 attn           : 8x8 circular conv + LN + gate -> O[2048][16384] fp16
//   K4 gemm_out       : Y = O @ Wo^T + bo, scatter NHWC + residual
// ---------------------------------------------------------------------------

#define Bb    2
#define Hh    256
#define Ww    256
#define Cc    32
#define HEADS 8
#define Mm    2048
#define Kq    2048
#define Ff    16384
#define Kf    16384
#define Nfin  2048

// ---- scratch ----
__device__ __align__(1024) __half g_A2[(size_t)Mm * Kq];           //   8 MB
__device__ __align__(1024) __half g_W2[(size_t)3 * Ff * Kq];       // 201 MB
__device__ __align__(1024) __half g_Wo2[(size_t)Nfin * Kf];        //  67 MB
__device__ float                  g_QKV[(size_t)3 * Mm * Ff];      // 402 MB
__device__ __align__(1024) __half g_O2[(size_t)Mm * Kf];           //  67 MB
__device__ float                  g_bP[3 * Ff + Nfin];             // permuted biases

// ---------------------------------------------------------------------------
// helpers
// ---------------------------------------------------------------------------
static __device__ __forceinline__ uint32_t s2u(const void* p) {
    uint32_t a;
    asm("{ .reg .u64 t; cvta.to.shared.u64 t, %1; cvt.u32.u64 %0, t; }"
        : "=r"(a) : "l"(p));
    return a;
}
static __device__ __forceinline__ void cpa16(uint32_t dst, const void* src) {
    asm volatile("cp.async.cg.shared.global [%0], [%1], 16;\n"
                 :: "r"(dst), "l"(src));
}
static __device__ __forceinline__ void cpa_commit() {
    asm volatile("cp.async.commit_group;\n");
}
template <int N>
static __device__ __forceinline__ void cpa_wait() {
    asm volatile("cp.async.wait_group %0;\n" :: "n"(N));
}
static __device__ __forceinline__ void ldm4(uint32_t* r, uint32_t a) {
    asm volatile("ldmatrix.sync.aligned.m8n8.x4.shared.b16 {%0,%1,%2,%3}, [%4];"
                 : "=r"(r[0]), "=r"(r[1]), "=r"(r[2]), "=r"(r[3]) : "r"(a));
}
static __device__ __forceinline__ void mma16816(float* d, const uint32_t* a,
                                                uint32_t b0, uint32_t b1) {
    asm volatile("mma.sync.aligned.m16n8k16.row.col.f32.f16.f16.f32 "
                 "{%0,%1,%2,%3}, {%4,%5,%6,%7}, {%8,%9}, {%0,%1,%2,%3};"
                 : "+f"(d[0]), "+f"(d[1]), "+f"(d[2]), "+f"(d[3])
                 : "r"(a[0]), "r"(a[1]), "r"(a[2]), "r"(a[3]), "r"(b0), "r"(b1));
}

// ---------------------------------------------------------------------------
// GEMM core: BM=128, BN=128, BK=64, 128 threads (4 warps 2x2, warp 64x64),
// 3-stage cp.async pipeline.  SMEM: 16x16 fp16 atoms (512B), atom (ka,i) at
// (ka*8+i)*512; element (row,col) at row*32 + ((col>>3 ^ (row>>2)&1)<<4)
// + (col&7)*2 — conflict-free for both cp.async stores and ldmatrix.
// ---------------------------------------------------------------------------
#define STG_A   16384
#define STG_SZ  32768
#define GSMEM   (3 * STG_SZ)

static __device__ __forceinline__ void load_stage(const __half* gA,
                                                  const __half* gB,
                                                  size_t K, int k0,
                                                  uint32_t base, int tid) {
#pragma unroll
    for (int it = 0; it < 8; it++) {           // A: 128 rows x 8 16B-chunks
        int q = it * 128 + tid;
        int m = q >> 3, h2 = q & 7;
        uint32_t dst = base + ((h2 >> 1) * 8 + (m >> 4)) * 512 + (m & 15) * 32
                     + (((h2 & 1) ^ ((m >> 2) & 1)) << 4);
        cpa16(dst, gA + (size_t)m * K + k0 + (h2 << 3));
    }
#pragma unroll
    for (int it = 0; it < 8; it++) {           // B: 128 rows x 8 16B-chunks
        int q = it * 128 + tid;
        int n = q >> 3, h2 = q & 7;
        uint32_t dst = base + STG_A + ((h2 >> 1) * 8 + (n >> 4)) * 512
                     + (n & 15) * 32 + (((h2 & 1) ^ ((n >> 2) & 1)) << 4);
        cpa16(dst, gB + (size_t)n * K + k0 + (h2 << 3));
    }
}

static __device__ __forceinline__ void compute_stage(uint32_t sbase, int wm, int wn,
                                                     uint32_t inAtom,
                                                     float acc[4][8][4]) {
    uint32_t abase = sbase + wm * (4 * 512) + inAtom;          // 4 m-atoms/warp
    uint32_t bbase = sbase + STG_A + wn * (4 * 512) + inAtom;  // 4 n-atoms/warp
#pragma unroll
    for (int ks = 0; ks < 4; ks++) {
        uint32_t af[4][4], bf[4][4];
#pragma unroll
        for (int am = 0; am < 4; am++) ldm4(af[am], abase + ks * 4096 + am * 512);
#pragma unroll
        for (int bi = 0; bi < 4; bi++) ldm4(bf[bi], bbase + ks * 4096 + bi * 512);
#pragma unroll
        for (int am = 0; am < 4; am++)
#pragma unroll
            for (int bi = 0; bi < 4; bi++) {
                mma16816(acc[am][bi * 2 + 0], af[am], bf[bi][0], bf[bi][2]);
                mma16816(acc[am][bi * 2 + 1], af[am], bf[bi][1], bf[bi][3]);
            }
    }
}

// Single-pass k-loop over K/64 chunks.
static __device__ __forceinline__ void gemm_mainloop(const __half* gA,
                                                     const __half* gB,
                                                     int K, uint32_t sb,
                                                     float acc[4][8][4]) {
    int tid = threadIdx.x, lane = tid & 31, wid = tid >> 5;
    int wm = wid & 1, wn = wid >> 1;
    int quad = lane >> 3;
    int lrow = ((quad & 1) << 3) + (lane & 7);
    int half = quad >> 1;
    uint32_t inAtom = lrow * 32 + ((half ^ ((lrow >> 2) & 1)) << 4);
    const int niter = K >> 6;

#pragma unroll
    for (int am = 0; am < 4; am++)
#pragma unroll
        for (int ni = 0; ni < 8; ni++)
#pragma unroll
            for (int j = 0; j < 4; j++) acc[am][ni][j] = 0.f;

    load_stage(gA, gB, K, 0, sb, tid);            cpa_commit();
    load_stage(gA, gB, K, 64, sb + STG_SZ, tid);  cpa_commit();

    int st = 0, st2 = 2;
    for (int i = 0; i < niter; i++) {
        if (i + 1 < niter) cpa_wait<1>(); else cpa_wait<0>();
        __syncthreads();
        if (i + 2 < niter) {
            load_stage(gA, gB, K, (i + 2) * 64, sb + st2 * STG_SZ, tid);
            cpa_commit();
        }
        compute_stage(sb + st * STG_SZ, wm, wn, inAtom, acc);
        st = (st == 2) ? 0 : st + 1;
        st2 = (st2 == 2) ? 0 : st2 + 1;
    }
}

// ---------------------------------------------------------------------------
// K0: transpose to fp16 with column permutation.
//   src fp32 [R][C] -> dst fp16 [C][R], dst row = perm(n).
//   mode 0 (QKV):  n = c*512+p0*64+p1*8+head -> n' = head*2048 + c*64 + pos
//   mode 1 (Wo):   n = c*64+p0*8+p1          -> n' = p0*256 + p1*32 + c
// ---------------------------------------------------------------------------
__global__ void __launch_bounds__(256)
transpose_half_kernel(const float* __restrict__ src,
                      __half* __restrict__ dst, int R, int C, int mode) {
    __shared__ float t[32][33];
    int tx = threadIdx.x, ty = threadIdx.y;
    int c0 = blockIdx.x * 32, r0 = blockIdx.y * 32;
#pragma unroll
    for (int i = 0; i < 4; i++)
        t[ty + i * 8][tx] = src[(size_t)(r0 + ty + i * 8) * C + c0 + tx];
    __syncthreads();
#pragma unroll
    for (int i = 0; i < 4; i++) {
        float v = t[tx][ty + i * 8];
        int n = c0 + ty + i * 8;
        int np = (mode == 0)
               ? ((n & 7) * 2048 + (n >> 9) * 64 + ((n >> 3) & 63))
               : (((n >> 3) & 7) * 256 + (n & 7) * 32 + (n >> 6));
        dst[(size_t)np * R + r0 + tx] = __float2half_rn(v);
    }
}

// Permute biases into the same column orders.
__global__ void __launch_bounds__(256)
perm_bias_kernel(const float* __restrict__ bq, const float* __restrict__ bk,
                 const float* __restrict__ bv, const float* __restrict__ bo) {
    int i = blockIdx.x * 256 + threadIdx.x;
    if (i < 3 * Ff) {
        int z = i >> 14, f = i & (Ff - 1);
        const float* s = (z == 0) ? bq : ((z == 1) ? bk : bv);
        int fp = (f & 7) * 2048 + (f >> 9) * 64 + ((f >> 3) & 63);
        g_bP[z * Ff + fp] = s[f];
    } else if (i < 3 * Ff + Nfin) {
        int f = i - 3 * Ff;
        int fp = ((f >> 3) & 7) * 256 + (f & 7) * 32 + (f >> 6);
        g_bP[3 * Ff + fp] = bo[f];
    }
}

// ---------------------------------------------------------------------------
// K1: LN over C=32 per pixel + im2col -> A fp16.  One warp per pixel.
// ---------------------------------------------------------------------------
__global__ void ln_im2col_kernel(const float* __restrict__ x,
                                 const float* __restrict__ gam,
                                 const float* __restrict__ bet) {
    int pix  = (blockIdx.x * blockDim.x + threadIdx.x) >> 5;
    int lane = threadIdx.x & 31;
    if (pix >= Bb * Hh * Ww) return;

    float v = x[(size_t)pix * Cc + lane];
    float mu = v;
#pragma unroll
    for (int o = 16; o; o >>= 1) mu += __shfl_xor_sync(0xffffffffu, mu, o);
    mu *= (1.0f / 32.0f);
    float d = v - mu;
    float var = d * d;
#pragma unroll
    for (int o = 16; o; o >>= 1) var += __shfl_xor_sync(0xffffffffu, var, o);
    var *= (1.0f / 32.0f);
    float xn = d * rsqrtf(var + 1e-6f) * gam[lane] + bet[lane];

    int w = pix % Ww;
    int h = (pix / Ww) % Hh;
    int b = pix / (Ww * Hh);
    int m = b * 1024 + (h >> 3) * 32 + (w >> 3);
    int k = (h & 7) * 256 + (w & 7) * 32 + lane;
    g_A2[(size_t)m * Kq + k] = __float2half_rn(xn);
}

// ---------------------------------------------------------------------------
// K2: Q/K/V GEMM.  grid (16, 128, 3); column-major raster -> B-tile L2 reuse.
// Output columns are permuted: f' = head*2048 + c*64 + pos.
// ---------------------------------------------------------------------------
__global__ void __launch_bounds__(128, 2)
gemm_qkv_kernel() {
    extern __shared__ char smem[];
    uint32_t sb = s2u(smem);
    int tid = threadIdx.x, lane = tid & 31, wid = tid >> 5;
    int wm = wid & 1, wn = wid >> 1;
    int bm = blockIdx.x * 128, bn = blockIdx.y * 128, z = blockIdx.z;

    const __half* gA = g_A2 + (size_t)bm * Kq;
    const __half* gB = g_W2 + ((size_t)z * Ff + bn) * Kq;

    float acc[4][8][4];
    gemm_mainloop(gA, gB, Kq, sb, acc);

    float* Cg = g_QKV + (size_t)z * Mm * Ff;
    const float* bias = g_bP + z * Ff;
    int g = lane >> 2, t = lane & 3;
#pragma unroll
    for (int am = 0; am < 4; am++)
#pragma unroll
        for (int rr = 0; rr < 2; rr++) {
            int row = bm + wm * 64 + am * 16 + rr * 8 + g;
            float* crow = Cg + (size_t)row * Ff;
#pragma unroll
            for (int ni = 0; ni < 8; ni++) {
                int fp = bn + wn * 64 + ni * 8 + t * 2;
                float2 bi2 = *(const float2*)(bias + fp);
                float2 o;
                o.x = acc[am][ni][rr * 2 + 0] + bi2.x;
                o.y = acc[am][ni][rr * 2 + 1] + bi2.y;
                *(float2*)(crow + fp) = o;
            }
        }
}

// ---------------------------------------------------------------------------
// K3: attention (8x8 circular conv) + LN + gate -> O fp16.
// QKV layout is head-major: Q[m][head*2048 + c*64 + pos] (coalesced).
// ---------------------------------------------------------------------------
__global__ void __launch_bounds__(256)
attn_kernel(const float* __restrict__ l2s, const float* __restrict__ l2b) {
    __shared__ float qs[32 * 64];
    __shared__ float ks[32 * 64];
    __shared__ float vs[32 * 68];
    __shared__ float outs[32 * 68];
    __shared__ float s2[32], b2[32], mus[64], rstds[64];

    int m = blockIdx.x;
    int head = blockIdx.y;
    int tid = threadIdx.x;

    const float* Q  = g_QKV + (size_t)m * Ff + head * 2048;
    const float* Kp = Q + (size_t)Mm * Ff;
    const float* V  = Q + (size_t)2 * Mm * Ff;

    if (tid < 32) { s2[tid] = l2s[tid]; b2[tid] = l2b[tid]; }

#pragma unroll
    for (int it = 0; it < 2; it++) {
        int i4 = it * 256 + tid;
        float4 qv = ((const float4*)Q)[i4];
        float4 kv = ((const float4*)Kp)[i4];
        float4 vv = ((const float4*)V)[i4];
        int idx = i4 * 4;
        *(float4*)&qs[idx] = qv;
        *(float4*)&ks[idx] = kv;
        int c = idx >> 6, pos = idx & 63;
        *(float4*)&vs[c * 68 + pos] = vv;
    }
    __syncthreads();

    float res[8];
#pragma unroll
    for (int j = 0; j < 8; j++) {
        int idx = j * 256 + tid;
        int c = idx >> 6, pos = idx & 63;
        int s = pos >> 3, t = pos & 7;
        const float* qc = &qs[c * 64];
        const float* kc = &ks[c * 64];
        float sum = 0.f;
#pragma unroll
        for (int u = 0; u < 8; u++) {
            int su = ((s - u) & 7) * 8;
#pragma unroll
            for (int v = 0; v < 8; v++)
                sum += qc[u * 8 + v] * kc[su + ((t - v) & 7)];
        }
        res[j] = sum;
    }
#pragma unroll
    for (int j = 0; j < 8; j++) {
        int idx = j * 256 + tid;
        int c = idx >> 6, pos = idx & 63;
        outs[c * 68 + pos] = res[j];
    }
    __syncthreads();

    if (tid < 64) {
        float mu = 0.f;
#pragma unroll
        for (int c = 0; c < 32; c++) mu += outs[c * 68 + tid];
        mu *= (1.0f / 32.0f);
        float var = 0.f;
#pragma unroll
        for (int c = 0; c < 32; c++) {
            float d = outs[c * 68 + tid] - mu;
            var += d * d;
        }
        var *= (1.0f / 32.0f);
        mus[tid] = mu;
        rstds[tid] = rsqrtf(var + 1e-6f);
    }
    __syncthreads();

    size_t Obase = (size_t)m * Kf;
#pragma unroll
    for (int it = 0; it < 8; it++) {
        int idx = it * 256 + tid;
        int c = idx & 31, pos = idx >> 5;
        int p0 = pos >> 3, p1 = pos & 7;
        float val = (outs[c * 68 + pos] - mus[pos]) * rstds[pos] * s2[c] + b2[c];
        float prod = vs[c * 68 + pos] * val;
        g_O2[Obase + p0 * 2048 + p1 * 256 + head * 32 + c] = __float2half_rn(prod);
    }
}

// ---------------------------------------------------------------------------
// K4: output GEMM + scatter + residual.  grid (16, 16).
// Output columns permuted: f2' = p0*256 + p1*32 + c  -> coalesced scatter.
// ---------------------------------------------------------------------------
__global__ void __launch_bounds__(128, 2)
gemm_out_kernel(const float* __restrict__ xin, float* __restrict__ out) {
    extern __shared__ char smem[];
    uint32_t sb = s2u(smem);
    int tid = threadIdx.x, lane = tid & 31, wid = tid >> 5;
    int wm = wid & 1, wn = wid >> 1;
    int bm = blockIdx.x * 128, bn = blockIdx.y * 128;

    const __half* gA = g_O2 + (size_t)bm * Kf;
    const __half* gB = g_Wo2 + (size_t)bn * Kf;

    float acc[4][8][4];
    gemm_mainloop(gA, gB, Kf, sb, acc);

    const float* bias = g_bP + 3 * Ff;
    int g = lane >> 2, t = lane & 3;
#pragma unroll
    for (int am = 0; am < 4; am++)
#pragma unroll
        for (int rr = 0; rr < 2; rr++) {
            int row = bm + wm * 64 + am * 16 + rr * 8 + g;
            int b_ = row >> 10, gh = (row >> 5) & 31, gw = row & 31;
#pragma unroll
            for (int ni = 0; ni < 8; ni++) {
                int fp = bn + wn * 64 + ni * 8 + t * 2;
                int c = fp & 31, p1 = (fp >> 5) & 7, p0 = (fp >> 8) & 7;
                size_t oi = (((size_t)(b_ * Hh + gh * 8 + p0)) * Ww
                             + gw * 8 + p1) * Cc + c;
                float2 xi = *(const float2*)(xin + oi);
                float2 bi2 = *(const float2*)(bias + fp);
                float2 o;
                o.x = acc[am][ni][rr * 2 + 0] + bi2.x + xi.x;
                o.y = acc[am][ni][rr * 2 + 1] + bi2.y + xi.y;
                *(float2*)(out + oi) = o;
            }
        }
}

// ---------------------------------------------------------------------------
extern "C" void kernel_launch(void* const* d_in, const int* in_sizes, int n_in,
                              void* d_out, int out_size) {
    const float* x   = (const float*)d_in[0];
    const float* l1s = (const float*)d_in[1];
    const float* l1b = (const float*)d_in[2];
    const float* Wq  = (const float*)d_in[3];
    const float* bq  = (const float*)d_in[4];
    const float* Wk  = (const float*)d_in[5];
    const float* bk  = (const float*)d_in[6];
    const float* Wv  = (const float*)d_in[7];
    const float* bv  = (const float*)d_in[8];
    const float* l2s = (const float*)d_in[9];
    const float* l2b = (const float*)d_in[10];
    const float* Wo  = (const float*)d_in[11];
    const float* bo  = (const float*)d_in[12];
    float* out = (float*)d_out;

    cudaFuncSetAttribute(gemm_qkv_kernel,
                         cudaFuncAttributeMaxDynamicSharedMemorySize, GSMEM);
    cudaFuncSetAttribute(gemm_out_kernel,
                         cudaFuncAttributeMaxDynamicSharedMemorySize, GSMEM);

    void *w2, *wo2;
    cudaGetSymbolAddress(&w2, g_W2);
    cudaGetSymbolAddress(&wo2, g_Wo2);

    dim3 tb(32, 8);
    const size_t WSZ = (size_t)Ff * Kq;
    transpose_half_kernel<<<dim3(512, 64), tb>>>(Wq, (__half*)w2, Kq, Ff, 0);
    transpose_half_kernel<<<dim3(512, 64), tb>>>(Wk, (__half*)w2 + WSZ, Kq, Ff, 0);
    transpose_half_kernel<<<dim3(512, 64), tb>>>(Wv, (__half*)w2 + 2 * WSZ, Kq, Ff, 0);
    transpose_half_kernel<<<dim3(64, 512), tb>>>(Wo, (__half*)wo2, Kf, Nfin, 1);

    perm_bias_kernel<<<(3 * Ff + Nfin + 255) / 256, 256>>>(bq, bk, bv, bo);

    ln_im2col_kernel<<<(Bb * Hh * Ww * 32) / 256, 256>>>(x, l1s, l1b);

    dim3 gq(16, 128, 3);
    gemm_qkv_kernel<<<gq, 128, GSMEM>>>();

    dim3 ga(Mm, HEADS);
    attn_kernel<<<ga, 256>>>(l2s, l2b);

    dim3 go(16, 16);
    gemm_out_kernel<<<go, 128, GSMEM>>>(x, out);
}

// round 16
// speedup vs baseline: 9.3822x; 1.0991x over previous
#include <cuda_runtime.h>
#include <cuda_fp16.h>
#include <cstdint>

// ---------------------------------------------------------------------------
// ImageFusion via single-pass fp16 mma.sync GEMMs (minimum-FLOP form).
//   K0 transpose_half : W[K][N] fp32 -> W[N][K] fp16 (columns permuted)
//   K1 ln_im2col      : LN(x) -> A[2048][2048] fp16
//   K2 gemm_qkv       : QKV fp32 = A @ W^T + b        (mma.sync fp16)
//   K3 attn           : 8x8 circular conv (row-register-blocked) + LN + gate
//   K4 gemm_out       : Y = O @ Wo^T + bo, scatter NHWC + residual
// Base-ISA only (ptxas targets sm_103 without 'a' features).
// ---------------------------------------------------------------------------

#define Bb    2
#define Hh    256
#define Ww    256
#define Cc    32
#define HEADS 8
#define Mm    2048
#define Kq    2048
#define Ff    16384
#define Kf    16384
#define Nfin  2048

// ---- scratch ----
__device__ __align__(1024) __half g_A2[(size_t)Mm * Kq];           //   8 MB
__device__ __align__(1024) __half g_W2[(size_t)3 * Ff * Kq];       // 201 MB
__device__ __align__(1024) __half g_Wo2[(size_t)Nfin * Kf];        //  67 MB
__device__ float                  g_QKV[(size_t)3 * Mm * Ff];      // 402 MB
__device__ __align__(1024) __half g_O2[(size_t)Mm * Kf];           //  67 MB
__device__ float                  g_bP[3 * Ff + Nfin];             // permuted biases

// ---------------------------------------------------------------------------
// helpers
// ---------------------------------------------------------------------------
static __device__ __forceinline__ uint32_t s2u(const void* p) {
    uint32_t a;
    asm("{ .reg .u64 t; cvta.to.shared.u64 t, %1; cvt.u32.u64 %0, t; }"
        : "=r"(a) : "l"(p));
    return a;
}
static __device__ __forceinline__ void cpa16(uint32_t dst, const void* src) {
    asm volatile("cp.async.cg.shared.global [%0], [%1], 16;\n"
                 :: "r"(dst), "l"(src));
}
static __device__ __forceinline__ void cpa_commit() {
    asm volatile("cp.async.commit_group;\n");
}
template <int N>
static __device__ __forceinline__ void cpa_wait() {
    asm volatile("cp.async.wait_group %0;\n" :: "n"(N));
}
static __device__ __forceinline__ void ldm4(uint32_t* r, uint32_t a) {
    asm volatile("ldmatrix.sync.aligned.m8n8.x4.shared.b16 {%0,%1,%2,%3}, [%4];"
                 : "=r"(r[0]), "=r"(r[1]), "=r"(r[2]), "=r"(r[3]) : "r"(a));
}
static __device__ __forceinline__ void mma16816(float* d, const uint32_t* a,
                                                uint32_t b0, uint32_t b1) {
    asm volatile("mma.sync.aligned.m16n8k16.row.col.f32.f16.f16.f32 "
                 "{%0,%1,%2,%3}, {%4,%5,%6,%7}, {%8,%9}, {%0,%1,%2,%3};"
                 : "+f"(d[0]), "+f"(d[1]), "+f"(d[2]), "+f"(d[3])
                 : "r"(a[0]), "r"(a[1]), "r"(a[2]), "r"(a[3]), "r"(b0), "r"(b1));
}

// ---------------------------------------------------------------------------
// GEMM core: BM=128, BN=128, BK=64, 128 threads (4 warps 2x2, warp 64x64),
// 3-stage cp.async pipeline.  (Validated at the HMMA issue floor.)
// ---------------------------------------------------------------------------
#define STG_A   16384
#define STG_SZ  32768
#define GSMEM   (3 * STG_SZ)

static __device__ __forceinline__ void load_stage(const __half* gA,
                                                  const __half* gB,
                                                  size_t K, int k0,
                                                  uint32_t base, int tid) {
#pragma unroll
    for (int it = 0; it < 8; it++) {           // A: 128 rows x 8 16B-chunks
        int q = it * 128 + tid;
        int m = q >> 3, h2 = q & 7;
        uint32_t dst = base + ((h2 >> 1) * 8 + (m >> 4)) * 512 + (m & 15) * 32
                     + (((h2 & 1) ^ ((m >> 2) & 1)) << 4);
        cpa16(dst, gA + (size_t)m * K + k0 + (h2 << 3));
    }
#pragma unroll
    for (int it = 0; it < 8; it++) {           // B: 128 rows x 8 16B-chunks
        int q = it * 128 + tid;
        int n = q >> 3, h2 = q & 7;
        uint32_t dst = base + STG_A + ((h2 >> 1) * 8 + (n >> 4)) * 512
                     + (n & 15) * 32 + (((h2 & 1) ^ ((n >> 2) & 1)) << 4);
        cpa16(dst, gB + (size_t)n * K + k0 + (h2 << 3));
    }
}

static __device__ __forceinline__ void compute_stage(uint32_t sbase, int wm, int wn,
                                                     uint32_t inAtom,
                                                     float acc[4][8][4]) {
    uint32_t abase = sbase + wm * (4 * 512) + inAtom;          // 4 m-atoms/warp
    uint32_t bbase = sbase + STG_A + wn * (4 * 512) + inAtom;  // 4 n-atoms/warp
#pragma unroll
    for (int ks = 0; ks < 4; ks++) {
        uint32_t af[4][4], bf[4][4];
#pragma unroll
        for (int am = 0; am < 4; am++) ldm4(af[am], abase + ks * 4096 + am * 512);
#pragma unroll
        for (int bi = 0; bi < 4; bi++) ldm4(bf[bi], bbase + ks * 4096 + bi * 512);
#pragma unroll
        for (int am = 0; am < 4; am++)
#pragma unroll
            for (int bi = 0; bi < 4; bi++) {
                mma16816(acc[am][bi * 2 + 0], af[am], bf[bi][0], bf[bi][2]);
                mma16816(acc[am][bi * 2 + 1], af[am], bf[bi][1], bf[bi][3]);
            }
    }
}

static __device__ __forceinline__ void gemm_mainloop(const __half* gA,
                                                     const __half* gB,
                                                     int K, uint32_t sb,
                                                     float acc[4][8][4]) {
    int tid = threadIdx.x, lane = tid & 31, wid = tid >> 5;
    int wm = wid & 1, wn = wid >> 1;
    int quad = lane >> 3;
    int lrow = ((quad & 1) << 3) + (lane & 7);
    int half = quad >> 1;
    uint32_t inAtom = lrow * 32 + ((half ^ ((lrow >> 2) & 1)) << 4);
    const int niter = K >> 6;

#pragma unroll
    for (int am = 0; am < 4; am++)
#pragma unroll
        for (int ni = 0; ni < 8; ni++)
#pragma unroll
            for (int j = 0; j < 4; j++) acc[am][ni][j] = 0.f;

    load_stage(gA, gB, K, 0, sb, tid);            cpa_commit();
    load_stage(gA, gB, K, 64, sb + STG_SZ, tid);  cpa_commit();

    int st = 0, st2 = 2;
    for (int i = 0; i < niter; i++) {
        if (i + 1 < niter) cpa_wait<1>(); else cpa_wait<0>();
        __syncthreads();
        if (i + 2 < niter) {
            load_stage(gA, gB, K, (i + 2) * 64, sb + st2 * STG_SZ, tid);
            cpa_commit();
        }
        compute_stage(sb + st * STG_SZ, wm, wn, inAtom, acc);
        st = (st == 2) ? 0 : st + 1;
        st2 = (st2 == 2) ? 0 : st2 + 1;
    }
}

// ---------------------------------------------------------------------------
// K0: transpose to fp16 with column permutation.
// ---------------------------------------------------------------------------
__global__ void __launch_bounds__(256)
transpose_half_kernel(const float* __restrict__ src,
                      __half* __restrict__ dst, int R, int C, int mode) {
    __shared__ float t[32][33];
    int tx = threadIdx.x, ty = threadIdx.y;
    int c0 = blockIdx.x * 32, r0 = blockIdx.y * 32;
#pragma unroll
    for (int i = 0; i < 4; i++)
        t[ty + i * 8][tx] = src[(size_t)(r0 + ty + i * 8) * C + c0 + tx];
    __syncthreads();
#pragma unroll
    for (int i = 0; i < 4; i++) {
        float v = t[tx][ty + i * 8];
        int n = c0 + ty + i * 8;
        int np = (mode == 0)
               ? ((n & 7) * 2048 + (n >> 9) * 64 + ((n >> 3) & 63))
               : (((n >> 3) & 7) * 256 + (n & 7) * 32 + (n >> 6));
        dst[(size_t)np * R + r0 + tx] = __float2half_rn(v);
    }
}

// Permute biases into the same column orders.
__global__ void __launch_bounds__(256)
perm_bias_kernel(const float* __restrict__ bq, const float* __restrict__ bk,
                 const float* __restrict__ bv, const float* __restrict__ bo) {
    int i = blockIdx.x * 256 + threadIdx.x;
    if (i < 3 * Ff) {
        int z = i >> 14, f = i & (Ff - 1);
        const float* s = (z == 0) ? bq : ((z == 1) ? bk : bv);
        int fp = (f & 7) * 2048 + (f >> 9) * 64 + ((f >> 3) & 63);
        g_bP[z * Ff + fp] = s[f];
    } else if (i < 3 * Ff + Nfin) {
        int f = i - 3 * Ff;
        int fp = ((f >> 3) & 7) * 256 + (f & 7) * 32 + (f >> 6);
        g_bP[3 * Ff + fp] = bo[f];
    }
}

// ---------------------------------------------------------------------------
// K1: LN over C=32 per pixel + im2col -> A fp16.  One warp per pixel.
// ---------------------------------------------------------------------------
__global__ void ln_im2col_kernel(const float* __restrict__ x,
                                 const float* __restrict__ gam,
                                 const float* __restrict__ bet) {
    int pix  = (blockIdx.x * blockDim.x + threadIdx.x) >> 5;
    int lane = threadIdx.x & 31;
    if (pix >= Bb * Hh * Ww) return;

    float v = x[(size_t)pix * Cc + lane];
    float mu = v;
#pragma unroll
    for (int o = 16; o; o >>= 1) mu += __shfl_xor_sync(0xffffffffu, mu, o);
    mu *= (1.0f / 32.0f);
    float d = v - mu;
    float var = d * d;
#pragma unroll
    for (int o = 16; o; o >>= 1) var += __shfl_xor_sync(0xffffffffu, var, o);
    var *= (1.0f / 32.0f);
    float xn = d * rsqrtf(var + 1e-6f) * gam[lane] + bet[lane];

    int w = pix % Ww;
    int h = (pix / Ww) % Hh;
    int b = pix / (Ww * Hh);
    int m = b * 1024 + (h >> 3) * 32 + (w >> 3);
    int k = (h & 7) * 256 + (w & 7) * 32 + lane;
    g_A2[(size_t)m * Kq + k] = __float2half_rn(xn);
}

// ---------------------------------------------------------------------------
// K2: Q/K/V GEMM.  grid (16, 128, 3); column-major raster -> B-tile L2 reuse.
// Output columns are permuted: f' = head*2048 + c*64 + pos.
// ---------------------------------------------------------------------------
__global__ void __launch_bounds__(128, 2)
gemm_qkv_kernel() {
    extern __shared__ char smem[];
    uint32_t sb = s2u(smem);
    int tid = threadIdx.x, lane = tid & 31, wid = tid >> 5;
    int wm = wid & 1, wn = wid >> 1;
    int bm = blockIdx.x * 128, bn = blockIdx.y * 128, z = blockIdx.z;

    const __half* gA = g_A2 + (size_t)bm * Kq;
    const __half* gB = g_W2 + ((size_t)z * Ff + bn) * Kq;

    float acc[4][8][4];
    gemm_mainloop(gA, gB, Kq, sb, acc);

    float* Cg = g_QKV + (size_t)z * Mm * Ff;
    const float* bias = g_bP + z * Ff;
    int g = lane >> 2, t = lane & 3;
#pragma unroll
    for (int am = 0; am < 4; am++)
#pragma unroll
        for (int rr = 0; rr < 2; rr++) {
            int row = bm + wm * 64 + am * 16 + rr * 8 + g;
            float* crow = Cg + (size_t)row * Ff;
#pragma unroll
            for (int ni = 0; ni < 8; ni++) {
                int fp = bn + wn * 64 + ni * 8 + t * 2;
                float2 bi2 = *(const float2*)(bias + fp);
                float2 o;
                o.x = acc[am][ni][rr * 2 + 0] + bi2.x;
                o.y = acc[am][ni][rr * 2 + 1] + bi2.y;
                *(float2*)(crow + fp) = o;
            }
        }
}

// ---------------------------------------------------------------------------
// K3: attention (8x8 circular conv, row-register-blocked) + LN + gate.
// Thread t handles (c = t>>3, s = t&7), computing all 8 outputs out[c][s][*]:
// per u: q-row and rotated k-row pulled into registers (float4 pairs), then
// 64 compile-time-indexed FFMAs.  32 LDS.128 + 512 FFMA per thread.
// All smem planes stride 68 (16B-aligned, bank-staggered across c).
// ---------------------------------------------------------------------------
__global__ void __launch_bounds__(256, 1)
attn_kernel(const float* __restrict__ l2s, const float* __restrict__ l2b) {
    __shared__ float qs[32 * 68];
    __shared__ float ks[32 * 68];
    __shared__ float vs[32 * 68];
    __shared__ float outs[32 * 68];
    __shared__ float s2[32], b2[32], mus[64], rstds[64];

    int m = blockIdx.x;
    int head = blockIdx.y;
    int tid = threadIdx.x;

    const float* Q  = g_QKV + (size_t)m * Ff + head * 2048;
    const float* Kp = Q + (size_t)Mm * Ff;
    const float* V  = Q + (size_t)2 * Mm * Ff;

    if (tid < 32) { s2[tid] = l2s[tid]; b2[tid] = l2b[tid]; }

#pragma unroll
    for (int it = 0; it < 2; it++) {
        int i4 = it * 256 + tid;                 // float4 index, idx = i4*4
        float4 qv = ((const float4*)Q)[i4];
        float4 kv = ((const float4*)Kp)[i4];
        float4 vv = ((const float4*)V)[i4];
        int idx = i4 * 4;
        int c = idx >> 6, pos = idx & 63;
        *(float4*)&qs[c * 68 + pos] = qv;
        *(float4*)&ks[c * 68 + pos] = kv;
        *(float4*)&vs[c * 68 + pos] = vv;
    }
    __syncthreads();

    // circular conv: out[c][s][t] = sum_{u,v} q[c][u][v] * k[c][(s-u)&7][(t-v)&7]
    {
        const int cc = tid >> 3, ss = tid & 7;
        const float* qc = &qs[cc * 68];
        const float* kc = &ks[cc * 68];
        float acc0 = 0.f, acc1 = 0.f, acc2 = 0.f, acc3 = 0.f;
        float acc4 = 0.f, acc5 = 0.f, acc6 = 0.f, acc7 = 0.f;
#pragma unroll
        for (int u = 0; u < 8; u++) {
            const float* krow = kc + (((ss - u) & 7) << 3);
            float4 qa = *(const float4*)(qc + (u << 3));
            float4 qb = *(const float4*)(qc + (u << 3) + 4);
            float4 ka = *(const float4*)(krow);
            float4 kb = *(const float4*)(krow + 4);
            float qv[8], kw[8];
            qv[0] = qa.x; qv[1] = qa.y; qv[2] = qa.z; qv[3] = qa.w;
            qv[4] = qb.x; qv[5] = qb.y; qv[6] = qb.z; qv[7] = qb.w;
            kw[0] = ka.x; kw[1] = ka.y; kw[2] = ka.z; kw[3] = ka.w;
            kw[4] = kb.x; kw[5] = kb.y; kw[6] = kb.z; kw[7] = kb.w;
#pragma unroll
            for (int v = 0; v < 8; v++) {
                float q = qv[v];
                acc0 += q * kw[(0 - v) & 7];
                acc1 += q * kw[(1 - v) & 7];
                acc2 += q * kw[(2 - v) & 7];
                acc3 += q * kw[(3 - v) & 7];
                acc4 += q * kw[(4 - v) & 7];
                acc5 += q * kw[(5 - v) & 7];
                acc6 += q * kw[(6 - v) & 7];
                acc7 += q * kw[(7 - v) & 7];
            }
        }
        float4 o0; o0.x = acc0; o0.y = acc1; o0.z = acc2; o0.w = acc3;
        float4 o1; o1.x = acc4; o1.y = acc5; o1.z = acc6; o1.w = acc7;
        *(float4*)&outs[cc * 68 + ss * 8]     = o0;
        *(float4*)&outs[cc * 68 + ss * 8 + 4] = o1;
    }
    __syncthreads();

    if (tid < 64) {
        float mu = 0.f;
#pragma unroll
        for (int c = 0; c < 32; c++) mu += outs[c * 68 + tid];
        mu *= (1.0f / 32.0f);
        float var = 0.f;
#pragma unroll
        for (int c = 0; c < 32; c++) {
            float d = outs[c * 68 + tid] - mu;
            var += d * d;
        }
        var *= (1.0f / 32.0f);
        mus[tid] = mu;
        rstds[tid] = rsqrtf(var + 1e-6f);
    }
    __syncthreads();

    size_t Obase = (size_t)m * Kf;
#pragma unroll
    for (int it = 0; it < 8; it++) {
        int idx = it * 256 + tid;
        int c = idx & 31, pos = idx >> 5;
        int p0 = pos >> 3, p1 = pos & 7;
        float val = (outs[c * 68 + pos] - mus[pos]) * rstds[pos] * s2[c] + b2[c];
        float prod = vs[c * 68 + pos] * val;
        g_O2[Obase + p0 * 2048 + p1 * 256 + head * 32 + c] = __float2half_rn(prod);
    }
}

// ---------------------------------------------------------------------------
// K4: output GEMM + scatter + residual.  grid (16, 16).
// Output columns permuted: f2' = p0*256 + p1*32 + c  -> coalesced scatter.
// ---------------------------------------------------------------------------
__global__ void __launch_bounds__(128, 2)
gemm_out_kernel(const float* __restrict__ xin, float* __restrict__ out) {
    extern __shared__ char smem[];
    uint32_t sb = s2u(smem);
    int tid = threadIdx.x, lane = tid & 31, wid = tid >> 5;
    int wm = wid & 1, wn = wid >> 1;
    int bm = blockIdx.x * 128, bn = blockIdx.y * 128;

    const __half* gA = g_O2 + (size_t)bm * Kf;
    const __half* gB = g_Wo2 + (size_t)bn * Kf;

    float acc[4][8][4];
    gemm_mainloop(gA, gB, Kf, sb, acc);

    const float* bias = g_bP + 3 * Ff;
    int g = lane >> 2, t = lane & 3;
#pragma unroll
    for (int am = 0; am < 4; am++)
#pragma unroll
        for (int rr = 0; rr < 2; rr++) {
            int row = bm + wm * 64 + am * 16 + rr * 8 + g;
            int b_ = row >> 10, gh = (row >> 5) & 31, gw = row & 31;
#pragma unroll
            for (int ni = 0; ni < 8; ni++) {
                int fp = bn + wn * 64 + ni * 8 + t * 2;
                int c = fp & 31, p1 = (fp >> 5) & 7, p0 = (fp >> 8) & 7;
                size_t oi = (((size_t)(b_ * Hh + gh * 8 + p0)) * Ww
                             + gw * 8 + p1) * Cc + c;
                float2 xi = *(const float2*)(xin + oi);
                float2 bi2 = *(const float2*)(bias + fp);
                float2 o;
                o.x = acc[am][ni][rr * 2 + 0] + bi2.x + xi.x;
                o.y = acc[am][ni][rr * 2 + 1] + bi2.y + xi.y;
                *(float2*)(out + oi) = o;
            }
        }
}

// ---------------------------------------------------------------------------
extern "C" void kernel_launch(void* const* d_in, const int* in_sizes, int n_in,
                              void* d_out, int out_size) {
    const float* x   = (const float*)d_in[0];
    const float* l1s = (const float*)d_in[1];
    const float* l1b = (const float*)d_in[2];
    const float* Wq  = (const float*)d_in[3];
    const float* bq  = (const float*)d_in[4];
    const float* Wk  = (const float*)d_in[5];
    const float* bk  = (const float*)d_in[6];
    const float* Wv  = (const float*)d_in[7];
    const float* bv  = (const float*)d_in[8];
    const float* l2s = (const float*)d_in[9];
    const float* l2b = (const float*)d_in[10];
    const float* Wo  = (const float*)d_in[11];
    const float* bo  = (const float*)d_in[12];
    float* out = (float*)d_out;

    cudaFuncSetAttribute(gemm_qkv_kernel,
                         cudaFuncAttributeMaxDynamicSharedMemorySize, GSMEM);
    cudaFuncSetAttribute(gemm_out_kernel,
                         cudaFuncAttributeMaxDynamicSharedMemorySize, GSMEM);

    void *w2, *wo2;
    cudaGetSymbolAddress(&w2, g_W2);
    cudaGetSymbolAddress(&wo2, g_Wo2);

    dim3 tb(32, 8);
    const size_t WSZ = (size_t)Ff * Kq;
    transpose_half_kernel<<<dim3(512, 64), tb>>>(Wq, (__half*)w2, Kq, Ff, 0);
    transpose_half_kernel<<<dim3(512, 64), tb>>>(Wk, (__half*)w2 + WSZ, Kq, Ff, 0);
    transpose_half_kernel<<<dim3(512, 64), tb>>>(Wv, (__half*)w2 + 2 * WSZ, Kq, Ff, 0);
    transpose_half_kernel<<<dim3(64, 512), tb>>>(Wo, (__half*)wo2, Kf, Nfin, 1);

    perm_bias_kernel<<<(3 * Ff + Nfin + 255) / 256, 256>>>(bq, bk, bv, bo);

    ln_im2col_kernel<<<(Bb * Hh * Ww * 32) / 256, 256>>>(x, l1s, l1b);

    dim3 gq(16, 128, 3);
    gemm_qkv_kernel<<<gq, 128, GSMEM>>>();

    dim3 ga(Mm, HEADS);
    attn_kernel<<<ga, 256>>>(l2s, l2b);

    dim3 go(16, 16);
    gemm_out_kernel<<<go, 128, GSMEM>>>(x, out);
}

// round 17
// speedup vs baseline: 9.5263x; 1.0154x over previous
#include <cuda_runtime.h>
#include <cuda_fp16.h>
#include <cstdint>

// ---------------------------------------------------------------------------
// ImageFusion via single-pass fp16 mma.sync GEMMs (minimum-FLOP form).
//   K0 transpose_half : W[K][N] fp32 -> W[N][K] fp16 (columns permuted)
//   K1 ln_im2col      : LN(x) -> A[2048][2048] fp16
//   K2 gemm_qkv       : QKV fp16 = A @ W^T + b        (mma.sync fp16)
//   K3 attn           : 8x8 circular conv (row-register-blocked) + LN + gate
//   K4 gemm_out       : Y = O @ Wo^T + bo, scatter NHWC + residual
// Base-ISA only (ptxas targets sm_103 without 'a' features).
// ---------------------------------------------------------------------------

#define Bb    2
#define Hh    256
#define Ww    256
#define Cc    32
#define HEADS 8
#define Mm    2048
#define Kq    2048
#define Ff    16384
#define Kf    16384
#define Nfin  2048

// ---- scratch ----
__device__ __align__(1024) __half g_A2[(size_t)Mm * Kq];           //   8 MB
__device__ __align__(1024) __half g_W2[(size_t)3 * Ff * Kq];       // 201 MB
__device__ __align__(1024) __half g_Wo2[(size_t)Nfin * Kf];        //  67 MB
__device__ __align__(1024) __half g_QKV[(size_t)3 * Mm * Ff];      // 201 MB
__device__ __align__(1024) __half g_O2[(size_t)Mm * Kf];           //  67 MB
__device__ float                  g_bP[3 * Ff + Nfin];             // permuted biases

// ---------------------------------------------------------------------------
// helpers
// ---------------------------------------------------------------------------
static __device__ __forceinline__ uint32_t s2u(const void* p) {
    uint32_t a;
    asm("{ .reg .u64 t; cvta.to.shared.u64 t, %1; cvt.u32.u64 %0, t; }"
        : "=r"(a) : "l"(p));
    return a;
}
static __device__ __forceinline__ void cpa16(uint32_t dst, const void* src) {
    asm volatile("cp.async.cg.shared.global [%0], [%1], 16;\n"
                 :: "r"(dst), "l"(src));
}
static __device__ __forceinline__ void cpa_commit() {
    asm volatile("cp.async.commit_group;\n");
}
template <int N>
static __device__ __forceinline__ void cpa_wait() {
    asm volatile("cp.async.wait_group %0;\n" :: "n"(N));
}
static __device__ __forceinline__ void ldm4(uint32_t* r, uint32_t a) {
    asm volatile("ldmatrix.sync.aligned.m8n8.x4.shared.b16 {%0,%1,%2,%3}, [%4];"
                 : "=r"(r[0]), "=r"(r[1]), "=r"(r[2]), "=r"(r[3]) : "r"(a));
}
static __device__ __forceinline__ void mma16816(float* d, const uint32_t* a,
                                                uint32_t b0, uint32_t b1) {
    asm volatile("mma.sync.aligned.m16n8k16.row.col.f32.f16.f16.f32 "
                 "{%0,%1,%2,%3}, {%4,%5,%6,%7}, {%8,%9}, {%0,%1,%2,%3};"
                 : "+f"(d[0]), "+f"(d[1]), "+f"(d[2]), "+f"(d[3])
                 : "r"(a[0]), "r"(a[1]), "r"(a[2]), "r"(a[3]), "r"(b0), "r"(b1));
}

// ---------------------------------------------------------------------------
// GEMM core: BM=128, BN=128, BK=64, 128 threads (4 warps 2x2, warp 64x64),
// 3-stage cp.async pipeline.  (Validated at the HMMA issue floor.)
// ---------------------------------------------------------------------------
#define STG_A   16384
#define STG_SZ  32768
#define GSMEM   (3 * STG_SZ)

static __device__ __forceinline__ void load_stage(const __half* gA,
                                                  const __half* gB,
                                                  size_t K, int k0,
                                                  uint32_t base, int tid) {
#pragma unroll
    for (int it = 0; it < 8; it++) {           // A: 128 rows x 8 16B-chunks
        int q = it * 128 + tid;
        int m = q >> 3, h2 = q & 7;
        uint32_t dst = base + ((h2 >> 1) * 8 + (m >> 4)) * 512 + (m & 15) * 32
                     + (((h2 & 1) ^ ((m >> 2) & 1)) << 4);
        cpa16(dst, gA + (size_t)m * K + k0 + (h2 << 3));
    }
#pragma unroll
    for (int it = 0; it < 8; it++) {           // B: 128 rows x 8 16B-chunks
        int q = it * 128 + tid;
        int n = q >> 3, h2 = q & 7;
        uint32_t dst = base + STG_A + ((h2 >> 1) * 8 + (n >> 4)) * 512
                     + (n & 15) * 32 + (((h2 & 1) ^ ((n >> 2) & 1)) << 4);
        cpa16(dst, gB + (size_t)n * K + k0 + (h2 << 3));
    }
}

static __device__ __forceinline__ void compute_stage(uint32_t sbase, int wm, int wn,
                                                     uint32_t inAtom,
                                                     float acc[4][8][4]) {
    uint32_t abase = sbase + wm * (4 * 512) + inAtom;          // 4 m-atoms/warp
    uint32_t bbase = sbase + STG_A + wn * (4 * 512) + inAtom;  // 4 n-atoms/warp
#pragma unroll
    for (int ks = 0; ks < 4; ks++) {
        uint32_t af[4][4], bf[4][4];
#pragma unroll
        for (int am = 0; am < 4; am++) ldm4(af[am], abase + ks * 4096 + am * 512);
#pragma unroll
        for (int bi = 0; bi < 4; bi++) ldm4(bf[bi], bbase + ks * 4096 + bi * 512);
#pragma unroll
        for (int am = 0; am < 4; am++)
#pragma unroll
            for (int bi = 0; bi < 4; bi++) {
                mma16816(acc[am][bi * 2 + 0], af[am], bf[bi][0], bf[bi][2]);
                mma16816(acc[am][bi * 2 + 1], af[am], bf[bi][1], bf[bi][3]);
            }
    }
}

static __device__ __forceinline__ void gemm_mainloop(const __half* gA,
                                                     const __half* gB,
                                                     int K, uint32_t sb,
                                                     float acc[4][8][4]) {
    int tid = threadIdx.x, lane = tid & 31, wid = tid >> 5;
    int wm = wid & 1, wn = wid >> 1;
    int quad = lane >> 3;
    int lrow = ((quad & 1) << 3) + (lane & 7);
    int half = quad >> 1;
    uint32_t inAtom = lrow * 32 + ((half ^ ((lrow >> 2) & 1)) << 4);
    const int niter = K >> 6;

#pragma unroll
    for (int am = 0; am < 4; am++)
#pragma unroll
        for (int ni = 0; ni < 8; ni++)
#pragma unroll
            for (int j = 0; j < 4; j++) acc[am][ni][j] = 0.f;

    load_stage(gA, gB, K, 0, sb, tid);            cpa_commit();
    load_stage(gA, gB, K, 64, sb + STG_SZ, tid);  cpa_commit();

    int st = 0, st2 = 2;
    for (int i = 0; i < niter; i++) {
        if (i + 1 < niter) cpa_wait<1>(); else cpa_wait<0>();
        __syncthreads();
        if (i + 2 < niter) {
            load_stage(gA, gB, K, (i + 2) * 64, sb + st2 * STG_SZ, tid);
            cpa_commit();
        }
        compute_stage(sb + st * STG_SZ, wm, wn, inAtom, acc);
        st = (st == 2) ? 0 : st + 1;
        st2 = (st2 == 2) ? 0 : st2 + 1;
    }
}

// ---------------------------------------------------------------------------
// K0: transpose to fp16 with column permutation, 64r x 32c tiles.
//   src fp32 [R][C] -> dst fp16 [C][R], dst row = perm(n).
//   Loads: 128B-coalesced fp32 rows.  Writes: half2, 128B/warp contiguous.
//   mode 0 (QKV, z selects Wq/Wk/Wv):  n' = head*2048 + c*64 + pos
//   mode 1 (Wo):                       n' = p0*256 + p1*32 + c
// ---------------------------------------------------------------------------
__global__ void __launch_bounds__(256)
transpose_half_kernel(const float* __restrict__ Wa, const float* __restrict__ Wb,
                      const float* __restrict__ Wc, __half* __restrict__ dst,
                      int R, int C, int mode) {
    __shared__ float t2[32][66];                 // [c'][r'], stride 66
    int tx = threadIdx.x, ty = threadIdx.y;      // (32, 8)
    int c0 = blockIdx.x * 32, r0 = blockIdx.y * 64;
    int z = blockIdx.z;
    const float* src = (z == 0) ? Wa : ((z == 1) ? Wb : Wc);
    __half* d = dst + (size_t)z * ((size_t)C * R);

#pragma unroll
    for (int i = 0; i < 8; i++) {
        int r = ty + i * 8;                      // 0..63
        t2[tx][r] = src[(size_t)(r0 + r) * C + c0 + tx];
    }
    __syncthreads();
#pragma unroll
    for (int i = 0; i < 4; i++) {
        int cp = ty + i * 8;                     // 0..31
        int n = c0 + cp;
        int np = (mode == 0)
               ? ((n & 7) * 2048 + (n >> 9) * 64 + ((n >> 3) & 63))
               : (((n >> 3) & 7) * 256 + (n & 7) * 32 + (n >> 6));
        float2 v = *(const float2*)&t2[cp][2 * tx];
        *(__half2*)(d + (size_t)np * R + r0 + 2 * tx) = __floats2half2_rn(v.x, v.y);
    }
}

// Permute biases into the same column orders.
__global__ void __launch_bounds__(256)
perm_bias_kernel(const float* __restrict__ bq, const float* __restrict__ bk,
                 const float* __restrict__ bv, const float* __restrict__ bo) {
    int i = blockIdx.x * 256 + threadIdx.x;
    if (i < 3 * Ff) {
        int z = i >> 14, f = i & (Ff - 1);
        const float* s = (z == 0) ? bq : ((z == 1) ? bk : bv);
        int fp = (f & 7) * 2048 + (f >> 9) * 64 + ((f >> 3) & 63);
        g_bP[z * Ff + fp] = s[f];
    } else if (i < 3 * Ff + Nfin) {
        int f = i - 3 * Ff;
        int fp = ((f >> 3) & 7) * 256 + (f & 7) * 32 + (f >> 6);
        g_bP[3 * Ff + fp] = bo[f];
    }
}

// ---------------------------------------------------------------------------
// K1: LN over C=32 per pixel + im2col -> A fp16.  One warp per pixel.
// ---------------------------------------------------------------------------
__global__ void ln_im2col_kernel(const float* __restrict__ x,
                                 const float* __restrict__ gam,
                                 const float* __restrict__ bet) {
    int pix  = (blockIdx.x * blockDim.x + threadIdx.x) >> 5;
    int lane = threadIdx.x & 31;
    if (pix >= Bb * Hh * Ww) return;

    float v = x[(size_t)pix * Cc + lane];
    float mu = v;
#pragma unroll
    for (int o = 16; o; o >>= 1) mu += __shfl_xor_sync(0xffffffffu, mu, o);
    mu *= (1.0f / 32.0f);
    float d = v - mu;
    float var = d * d;
#pragma unroll
    for (int o = 16; o; o >>= 1) var += __shfl_xor_sync(0xffffffffu, var, o);
    var *= (1.0f / 32.0f);
    float xn = d * rsqrtf(var + 1e-6f) * gam[lane] + bet[lane];

    int w = pix % Ww;
    int h = (pix / Ww) % Hh;
    int b = pix / (Ww * Hh);
    int m = b * 1024 + (h >> 3) * 32 + (w >> 3);
    int k = (h & 7) * 256 + (w & 7) * 32 + lane;
    g_A2[(size_t)m * Kq + k] = __float2half_rn(xn);
}

// ---------------------------------------------------------------------------
// K2: Q/K/V GEMM.  grid (16, 128, 3); column-major raster -> B-tile L2 reuse.
// Output columns are permuted: f' = head*2048 + c*64 + pos.  fp16 output.
// ---------------------------------------------------------------------------
__global__ void __launch_bounds__(128, 2)
gemm_qkv_kernel() {
    extern __shared__ char smem[];
    uint32_t sb = s2u(smem);
    int tid = threadIdx.x, lane = tid & 31, wid = tid >> 5;
    int wm = wid & 1, wn = wid >> 1;
    int bm = blockIdx.x * 128, bn = blockIdx.y * 128, z = blockIdx.z;

    const __half* gA = g_A2 + (size_t)bm * Kq;
    const __half* gB = g_W2 + ((size_t)z * Ff + bn) * Kq;

    float acc[4][8][4];
    gemm_mainloop(gA, gB, Kq, sb, acc);

    __half* Cg = g_QKV + (size_t)z * Mm * Ff;
    const float* bias = g_bP + z * Ff;
    int g = lane >> 2, t = lane & 3;
#pragma unroll
    for (int am = 0; am < 4; am++)
#pragma unroll
        for (int rr = 0; rr < 2; rr++) {
            int row = bm + wm * 64 + am * 16 + rr * 8 + g;
            __half* crow = Cg + (size_t)row * Ff;
#pragma unroll
            for (int ni = 0; ni < 8; ni++) {
                int fp = bn + wn * 64 + ni * 8 + t * 2;
                float2 bi2 = *(const float2*)(bias + fp);
                float ox = acc[am][ni][rr * 2 + 0] + bi2.x;
                float oy = acc[am][ni][rr * 2 + 1] + bi2.y;
                *(__half2*)(crow + fp) = __floats2half2_rn(ox, oy);
            }
        }
}

// ---------------------------------------------------------------------------
// K3: attention (8x8 circular conv, row-register-blocked) + LN + gate.
// QKV is fp16, head-major: Q[m][head*2048 + c*64 + pos] (coalesced uint4).
// ---------------------------------------------------------------------------
__global__ void __launch_bounds__(256, 1)
attn_kernel(const float* __restrict__ l2s, const float* __restrict__ l2b) {
    __shared__ float qs[32 * 68];
    __shared__ float ks[32 * 68];
    __shared__ float vs[32 * 68];
    __shared__ float outs[32 * 68];
    __shared__ float s2[32], b2[32], mus[64], rstds[64];

    int m = blockIdx.x;
    int head = blockIdx.y;
    int tid = threadIdx.x;

    const __half* Q  = g_QKV + (size_t)m * Ff + head * 2048;
    const __half* Kp = Q + (size_t)Mm * Ff;
    const __half* V  = Q + (size_t)2 * Mm * Ff;

    if (tid < 32) { s2[tid] = l2s[tid]; b2[tid] = l2b[tid]; }

    // load: one uint4 (8 halves) per plane per thread; convert to fp32 smem
    {
        uint4 qv = ((const uint4*)Q)[tid];
        uint4 kv = ((const uint4*)Kp)[tid];
        uint4 vv = ((const uint4*)V)[tid];
        int idx = tid * 8;
        int c = idx >> 6, pos = idx & 63;
        const __half2* qh = (const __half2*)&qv;
        const __half2* kh = (const __half2*)&kv;
        const __half2* vh = (const __half2*)&vv;
        float2 q0 = __half22float2(qh[0]), q1 = __half22float2(qh[1]);
        float2 q2 = __half22float2(qh[2]), q3 = __half22float2(qh[3]);
        float2 k0 = __half22float2(kh[0]), k1 = __half22float2(kh[1]);
        float2 k2 = __half22float2(kh[2]), k3 = __half22float2(kh[3]);
        float2 v0 = __half22float2(vh[0]), v1 = __half22float2(vh[1]);
        float2 v2 = __half22float2(vh[2]), v3 = __half22float2(vh[3]);
        float4 a; float4 b;
        a.x = q0.x; a.y = q0.y; a.z = q1.x; a.w = q1.y;
        b.x = q2.x; b.y = q2.y; b.z = q3.x; b.w = q3.y;
        *(float4*)&qs[c * 68 + pos] = a;
        *(float4*)&qs[c * 68 + pos + 4] = b;
        a.x = k0.x; a.y = k0.y; a.z = k1.x; a.w = k1.y;
        b.x = k2.x; b.y = k2.y; b.z = k3.x; b.w = k3.y;
        *(float4*)&ks[c * 68 + pos] = a;
        *(float4*)&ks[c * 68 + pos + 4] = b;
        a.x = v0.x; a.y = v0.y; a.z = v1.x; a.w = v1.y;
        b.x = v2.x; b.y = v2.y; b.z = v3.x; b.w = v3.y;
        *(float4*)&vs[c * 68 + pos] = a;
        *(float4*)&vs[c * 68 + pos + 4] = b;
    }
    __syncthreads();

    // circular conv: out[c][s][t] = sum_{u,v} q[c][u][v] * k[c][(s-u)&7][(t-v)&7]
    {
        const int cc = tid >> 3, ss = tid & 7;
        const float* qc = &qs[cc * 68];
        const float* kc = &ks[cc * 68];
        float acc0 = 0.f, acc1 = 0.f, acc2 = 0.f, acc3 = 0.f;
        float acc4 = 0.f, acc5 = 0.f, acc6 = 0.f, acc7 = 0.f;
#pragma unroll
        for (int u = 0; u < 8; u++) {
            const float* krow = kc + (((ss - u) & 7) << 3);
            float4 qa = *(const float4*)(qc + (u << 3));
            float4 qb = *(const float4*)(qc + (u << 3) + 4);
            float4 ka = *(const float4*)(krow);
            float4 kb = *(const float4*)(krow + 4);
            float qv[8], kw[8];
            qv[0] = qa.x; qv[1] = qa.y; qv[2] = qa.z; qv[3] = qa.w;
            qv[4] = qb.x; qv[5] = qb.y; qv[6] = qb.z; qv[7] = qb.w;
            kw[0] = ka.x; kw[1] = ka.y; kw[2] = ka.z; kw[3] = ka.w;
            kw[4] = kb.x; kw[5] = kb.y; kw[6] = kb.z; kw[7] = kb.w;
#pragma unroll
            for (int v = 0; v < 8; v++) {
                float q = qv[v];
                acc0 += q * kw[(0 - v) & 7];
                acc1 += q * kw[(1 - v) & 7];
                acc2 += q * kw[(2 - v) & 7];
                acc3 += q * kw[(3 - v) & 7];
                acc4 += q * kw[(4 - v) & 7];
                acc5 += q * kw[(5 - v) & 7];
                acc6 += q * kw[(6 - v) & 7];
                acc7 += q * kw[(7 - v) & 7];
            }
        }
        float4 o0; o0.x = acc0; o0.y = acc1; o0.z = acc2; o0.w = acc3;
        float4 o1; o1.x = acc4; o1.y = acc5; o1.z = acc6; o1.w = acc7;
        *(float4*)&outs[cc * 68 + ss * 8]     = o0;
        *(float4*)&outs[cc * 68 + ss * 8 + 4] = o1;
    }
    __syncthreads();

    // LN stats over c per position: 4 threads per pos + quad shfl reduce
    {
        int pos = tid >> 2, part = tid & 3;
        float sum = 0.f, sq = 0.f;
#pragma unroll
        for (int j = 0; j < 8; j++) {
            float v = outs[(part * 8 + j) * 68 + pos];
            sum += v; sq += v * v;
        }
        sum += __shfl_xor_sync(0xffffffffu, sum, 1);
        sq  += __shfl_xor_sync(0xffffffffu, sq, 1);
        sum += __shfl_xor_sync(0xffffffffu, sum, 2);
        sq  += __shfl_xor_sync(0xffffffffu, sq, 2);
        if (part == 0) {
            float mu = sum * (1.0f / 32.0f);
            float var = sq * (1.0f / 32.0f) - mu * mu;
            mus[pos] = mu;
            rstds[pos] = rsqrtf(var + 1e-6f);
        }
    }
    __syncthreads();

    size_t Obase = (size_t)m * Kf;
#pragma unroll
    for (int it = 0; it < 8; it++) {
        int idx = it * 256 + tid;
        int c = idx & 31, pos = idx >> 5;
        int p0 = pos >> 3, p1 = pos & 7;
        float val = (outs[c * 68 + pos] - mus[pos]) * rstds[pos] * s2[c] + b2[c];
        float prod = vs[c * 68 + pos] * val;
        g_O2[Obase + p0 * 2048 + p1 * 256 + head * 32 + c] = __float2half_rn(prod);
    }
}

// ---------------------------------------------------------------------------
// K4: output GEMM + scatter + residual.  grid (16, 16).
// Output columns permuted: f2' = p0*256 + p1*32 + c  -> coalesced scatter.
// ---------------------------------------------------------------------------
__global__ void __launch_bounds__(128, 2)
gemm_out_kernel(const float* __restrict__ xin, float* __restrict__ out) {
    extern __shared__ char smem[];
    uint32_t sb = s2u(smem);
    int tid = threadIdx.x, lane = tid & 31, wid = tid >> 5;
    int wm = wid & 1, wn = wid >> 1;
    int bm = blockIdx.x * 128, bn = blockIdx.y * 128;

    const __half* gA = g_O2 + (size_t)bm * Kf;
    const __half* gB = g_Wo2 + (size_t)bn * Kf;

    float acc[4][8][4];
    gemm_mainloop(gA, gB, Kf, sb, acc);

    const float* bias = g_bP + 3 * Ff;
    int g = lane >> 2, t = lane & 3;
#pragma unroll
    for (int am = 0; am < 4; am++)
#pragma unroll
        for (int rr = 0; rr < 2; rr++) {
            int row = bm + wm * 64 + am * 16 + rr * 8 + g;
            int b_ = row >> 10, gh = (row >> 5) & 31, gw = row & 31;
#pragma unroll
            for (int ni = 0; ni < 8; ni++) {
                int fp = bn + wn * 64 + ni * 8 + t * 2;
                int c = fp & 31, p1 = (fp >> 5) & 7, p0 = (fp >> 8) & 7;
                size_t oi = (((size_t)(b_ * Hh + gh * 8 + p0)) * Ww
                             + gw * 8 + p1) * Cc + c;
                float2 xi = *(const float2*)(xin + oi);
                float2 bi2 = *(const float2*)(bias + fp);
                float2 o;
                o.x = acc[am][ni][rr * 2 + 0] + bi2.x + xi.x;
                o.y = acc[am][ni][rr * 2 + 1] + bi2.y + xi.y;
                *(float2*)(out + oi) = o;
            }
        }
}

// ---------------------------------------------------------------------------
extern "C" void kernel_launch(void* const* d_in, const int* in_sizes, int n_in,
                              void* d_out, int out_size) {
    const float* x   = (const float*)d_in[0];
    const float* l1s = (const float*)d_in[1];
    const float* l1b = (const float*)d_in[2];
    const float* Wq  = (const float*)d_in[3];
    const float* bq  = (const float*)d_in[4];
    const float* Wk  = (const float*)d_in[5];
    const float* bk  = (const float*)d_in[6];
    const float* Wv  = (const float*)d_in[7];
    const float* bv  = (const float*)d_in[8];
    const float* l2s = (const float*)d_in[9];
    const float* l2b = (const float*)d_in[10];
    const float* Wo  = (const float*)d_in[11];
    const float* bo  = (const float*)d_in[12];
    float* out = (float*)d_out;

    cudaFuncSetAttribute(gemm_qkv_kernel,
                         cudaFuncAttributeMaxDynamicSharedMemorySize, GSMEM);
    cudaFuncSetAttribute(gemm_out_kernel,
                         cudaFuncAttributeMaxDynamicSharedMemorySize, GSMEM);

    void *w2, *wo2;
    cudaGetSymbolAddress(&w2, g_W2);
    cudaGetSymbolAddress(&wo2, g_Wo2);

    dim3 tb(32, 8);
    // QKV weights fused: grid (Ff/32, Kq/64, 3)
    transpose_half_kernel<<<dim3(512, 32, 3), tb>>>(Wq, Wk, Wv, (__half*)w2,
                                                    Kq, Ff, 0);
    // Wo: grid (Nfin/32, Kf/64)
    transpose_half_kernel<<<dim3(64, 256, 1), tb>>>(Wo, Wo, Wo, (__half*)wo2,
                                                    Kf, Nfin, 1);

    perm_bias_kernel<<<(3 * Ff + Nfin + 255) / 256, 256>>>(bq, bk, bv, bo);

    ln_im2col_kernel<<<(Bb * Hh * Ww * 32) / 256, 256>>>(x, l1s, l1b);

    dim3 gq(16, 128, 3);
    gemm_qkv_kernel<<<gq, 128, GSMEM>>>();

    dim3 ga(Mm, HEADS);
    attn_kernel<<<ga, 256>>>(l2s, l2b);

    dim3 go(16, 16);
    gemm_out_kernel<<<go, 128, GSMEM>>>(x, out);
}